// round 4
// baseline (speedup 1.0000x reference)
#include <cuda_runtime.h>
#include <math.h>
#include <stdint.h>

#define N_NODES 2000
#define NFEAT   128
#define LB      128
#define TFEAT   36
#define FC1     256
#define DELTA_MIN 0.05f

// ---------------- scratch (device globals; no allocation) ----------------
__device__ float g_accP[25][FC1 * LB];     // split-K partials, [split][t*256 + k]
__device__ float g_HsT[FC1 * LB];          // relu spatial hidden, [k][t]
__device__ float g_HtT[FC1 * LB];          // relu temporal hidden, [k][t]
__device__ float g_U1[N_NODES * LB];       // U[:,:,i1]  [n][t]  (tf32-rounded)
__device__ float g_U2[N_NODES * LB];       // U[:,:,i2]  [n][t]  (full fp32)
__device__ float g_P [N_NODES * LB];       // U2 @ B^T   [m][f]  (tf32-rounded)

__device__ __forceinline__ float to_tf32(float x) {
    uint32_t u;
    asm("cvt.rna.tf32.f32 %0, %1;" : "=r"(u) : "f"(x));
    return __uint_as_float(u);
}
__device__ __forceinline__ double pack2(float x, float y) {
    double d; asm("mov.b64 %0, {%1, %2};" : "=d"(d) : "f"(x), "f"(y)); return d;
}
__device__ __forceinline__ void fma2(double& acc, double a, double b) {
    asm("fma.rn.f32x2 %0, %1, %2, %0;" : "+d"(acc) : "d"(a), "d"(b));
}
__device__ __forceinline__ float2 unpack2(double d) {
    float2 r; asm("mov.b64 {%0, %1}, %2;" : "=f"(r.x), "=f"(r.y) : "d"(d)); return r;
}
__device__ __forceinline__ void cp_async16(uint32_t dst, const void* src, int ssize) {
    asm volatile("cp.async.ca.shared.global [%0], [%1], 16, %2;"
                 :: "r"(dst), "l"(src), "r"(ssize));
}

// ---------------- kernel 1: spatial hidden, split-K, coalesced ------------
// grid (8 k-tiles of 32, 25 j-splits of 80), block 256
__global__ __launch_bounds__(256) void k_hid_s(const float* __restrict__ li,
                                               const float* __restrict__ Ws1) {
    __shared__ float smA[16 * 132];   // [jj][t], pad 132
    __shared__ float smW[16 * 36];    // [jj][kk], pad 36
    const int k0 = blockIdx.x * 32;
    const int j0 = blockIdx.y * 80;
    const int tid = threadIdx.x;
    const int tx = tid & 7;
    const int ty = tid >> 3;

    float acc[4][4];
#pragma unroll
    for (int u = 0; u < 4; u++)
#pragma unroll
        for (int v = 0; v < 4; v++) acc[u][v] = 0.f;

    for (int jb = 0; jb < 80; jb += 16) {
        __syncthreads();
#pragma unroll
        for (int it = 0; it < 8; it++) {
            int e = tid + it * 256;
            int t = e >> 4, jj = e & 15;
            smA[jj * 132 + t] = li[t * N_NODES + j0 + jb + jj];
        }
#pragma unroll
        for (int it = 0; it < 2; it++) {
            int e = tid + it * 256;
            int jj = e >> 5, kk = e & 31;
            smW[jj * 36 + kk] = Ws1[(j0 + jb + jj) * FC1 + k0 + kk];
        }
        __syncthreads();
#pragma unroll
        for (int jj = 0; jj < 16; jj++) {
            float4 a = *(const float4*)&smA[jj * 132 + ty * 4];
            float4 w = *(const float4*)&smW[jj * 36 + tx * 4];
            float av[4] = {a.x, a.y, a.z, a.w};
            float wv[4] = {w.x, w.y, w.z, w.w};
#pragma unroll
            for (int u = 0; u < 4; u++)
#pragma unroll
                for (int v = 0; v < 4; v++) acc[u][v] += av[u] * wv[v];
        }
    }
    const int sp = blockIdx.y;
#pragma unroll
    for (int u = 0; u < 4; u++) {
        int t = ty * 4 + u;
        float4 v = make_float4(acc[u][0], acc[u][1], acc[u][2], acc[u][3]);
        *(float4*)&g_accP[sp][t * FC1 + k0 + tx * 4] = v;
    }
}

// ---------------- kernel 2: finalize spatial + temporal hidden ------------
// grid 128 (t), block 256 (k)
__global__ void k_hid_fin(const float* __restrict__ tf, const float* __restrict__ Wt1,
                          const float* __restrict__ bs1, const float* __restrict__ bt1) {
    const int t = blockIdx.x;
    const int k = threadIdx.x;
    __shared__ float stf[TFEAT];
    if (k < TFEAT) stf[k] = tf[t * TFEAT + k];

    float hs = bs1[k];
#pragma unroll
    for (int s = 0; s < 25; s++) hs += g_accP[s][t * FC1 + k];
    g_HsT[k * 128 + t] = fmaxf(hs, 0.f);

    __syncthreads();
    float a = bt1[k];
#pragma unroll
    for (int j = 0; j < TFEAT; j++)
        a += stf[j] * Wt1[j * FC1 + k];
    g_HtT[k * 128 + t] = fmaxf(a, 0.f);
}

// ---------------- kernel 3: embed gathered cols -> U1, U2 -----------------
// grid 500 (4 nodes each = 8 cols), block 256 = (t 0..127) x (col-half h 0..1)
__global__ __launch_bounds__(256) void k_embed(
    const float* __restrict__ Ws2, const float* __restrict__ bs2,
    const float* __restrict__ Wt2, const float* __restrict__ bt2,
    const int* __restrict__ idxp, const int* __restrict__ tdp) {

    __shared__ float smWs[256 * 8];    // [k][cc]   8 KB
    __shared__ float smWt[256 * 8];    //           8 KB
    __shared__ float smHs[32 * 128];   // [kk][t]  16 KB
    __shared__ float smHt[32 * 128];   //          16 KB
    __shared__ float smBs[8], smBt[8];

    const int idx = idxp[0];
    const int td  = tdp[0];
    const int i1  = (td >= 0) ? (idx - td) : idx;
    const int i2  = (td >= 0) ? idx        : (idx + td);

    const int n0  = blockIdx.x * 4;
    const int tid = threadIdx.x;

    // gather 8 columns of Ws2/Wt2 (scattered DRAM)
#pragma unroll
    for (int it = 0; it < 8; it++) {
        int e = tid + it * 256;
        int k = e >> 3, cc = e & 7;
        int c = (n0 + (cc >> 1)) * NFEAT + ((cc & 1) ? i2 : i1);
        smWs[e] = Ws2[(long)k * (N_NODES * NFEAT) + c];
        smWt[e] = Wt2[(long)k * (N_NODES * NFEAT) + c];
    }
    if (tid < 8) {
        int c = (n0 + (tid >> 1)) * NFEAT + ((tid & 1) ? i2 : i1);
        smBs[tid] = bs2[c];
        smBt[tid] = bt2[c];
    }

    const int t = tid & 127;
    const int h = tid >> 7;    // cols h*4 .. h*4+3

    double accS01 = 0.0, accS23 = 0.0, accT01 = 0.0, accT23 = 0.0;

    for (int kc = 0; kc < 256; kc += 32) {
        __syncthreads();
        // stage Hs/Ht chunk [32 k][128 t]
#pragma unroll
        for (int it = 0; it < 4; it++) {
            int e4 = tid + it * 256;
            int kk = e4 >> 5, tt = (e4 & 31) * 4;
            *(float4*)&smHs[kk * 128 + tt] = *(const float4*)&g_HsT[(kc + kk) * 128 + tt];
            *(float4*)&smHt[kk * 128 + tt] = *(const float4*)&g_HtT[(kc + kk) * 128 + tt];
        }
        __syncthreads();
#pragma unroll 8
        for (int kk = 0; kk < 32; kk++) {
            float hs = smHs[kk * 128 + t];
            float ht = smHt[kk * 128 + t];
            double hh = pack2(hs, hs);
            double h2 = pack2(ht, ht);
            double2 ws = *(const double2*)&smWs[(kc + kk) * 8 + h * 4];
            double2 wt = *(const double2*)&smWt[(kc + kk) * 8 + h * 4];
            fma2(accS01, hh, ws.x);
            fma2(accS23, hh, ws.y);
            fma2(accT01, h2, wt.x);
            fma2(accT23, h2, wt.y);
        }
    }

    float2 s01 = unpack2(accS01), s23 = unpack2(accS23);
    float2 t01 = unpack2(accT01), t23 = unpack2(accT23);
    float sv[4] = {s01.x, s01.y, s23.x, s23.y};
    float tv[4] = {t01.x, t01.y, t23.x, t23.y};
#pragma unroll
    for (int q = 0; q < 4; q++) {
        int col = h * 4 + q;
        float v = fmaxf(sv[q] + smBs[col], 0.f) + fmaxf(tv[q] + smBt[col], 0.f);
        int n = n0 + (col >> 1);
        if (col & 1) g_U2[n * 128 + t] = v;            // fp32 -> P
        else         g_U1[n * 128 + t] = to_tf32(v);   // tf32 -> mma A
    }
}

// ---------------- kernel 4: P = U2 @ B^T ----------------------------------
// grid 250 (8 rows each), block 256 = (f 0..127) x (row-half rh 0..1)
__global__ __launch_bounds__(256) void k_u2b(const float* __restrict__ B) {
    __shared__ float smB[128 * 36];    // [f][g-chunk 32], pad 36: 18 KB
    __shared__ float smU[8 * 128];     // [r][g]: 4 KB
    const int m0  = blockIdx.x * 8;
    const int tid = threadIdx.x;
    const int f   = tid & 127;
    const int rh  = tid >> 7;

    // stage the 8 U2 rows
    {
        int r = tid >> 5, t4 = (tid & 31) * 4;
        *(float4*)&smU[r * 128 + t4] = *(const float4*)&g_U2[(m0 + r) * 128 + t4];
    }

    float acc[4];
#pragma unroll
    for (int q = 0; q < 4; q++) acc[q] = 0.f;

    for (int gc = 0; gc < 128; gc += 32) {
        __syncthreads();
#pragma unroll
        for (int it = 0; it < 4; it++) {
            int e = tid + it * 256;
            int fr = e >> 3, g4 = (e & 7) * 4;
            *(float4*)&smB[fr * 36 + g4] = *(const float4*)&B[fr * 128 + gc + g4];
        }
        __syncthreads();
#pragma unroll
        for (int gi = 0; gi < 8; gi++) {
            float4 b = *(const float4*)&smB[f * 36 + gi * 4];
#pragma unroll
            for (int rr = 0; rr < 4; rr++) {
                float4 u = *(const float4*)&smU[(rh * 4 + rr) * 128 + gc + gi * 4];
                acc[rr] += u.x * b.x + u.y * b.y + u.z * b.z + u.w * b.w;
            }
        }
    }
#pragma unroll
    for (int rr = 0; rr < 4; rr++)
        g_P[(m0 + rh * 4 + rr) * 128 + f] = to_tf32(acc[rr]);
}

// ---------------- kernel 5: x = U1 @ P^T (tf32, cp.async double-buffer) ---
#define MMA_TF32(c, a, b)                                                          \
    asm volatile("mma.sync.aligned.m16n8k8.row.col.f32.tf32.tf32.f32 "             \
                 "{%0,%1,%2,%3},{%4,%5,%6,%7},{%8,%9},{%0,%1,%2,%3};"              \
                 : "+f"(c[0]), "+f"(c[1]), "+f"(c[2]), "+f"(c[3])                  \
                 : "r"(a[0]), "r"(a[1]), "r"(a[2]), "r"(b[0]), "r"(b[1]))
// NOTE: macro above must carry all 4 a regs:
#undef MMA_TF32
#define MMA_TF32(c, a, b)                                                          \
    asm volatile("mma.sync.aligned.m16n8k8.row.col.f32.tf32.tf32.f32 "             \
                 "{%0,%1,%2,%3},{%4,%5,%6,%7},{%8,%9},{%0,%1,%2,%3};"              \
                 : "+f"(c[0]), "+f"(c[1]), "+f"(c[2]), "+f"(c[3])                  \
                 : "r"(a[0]), "r"(a[1]), "r"(a[2]), "r"(a[3]), "r"(b[0]), "r"(b[1]))

__global__ __launch_bounds__(256, 2) void k_gemm(float* __restrict__ out) {
    __shared__ float smA[2][128 * 20];   // [buf][row][k-chunk 16], pad 20
    __shared__ float smB[2][128 * 20];
    const int n0 = blockIdx.y * 128;
    const int m0 = blockIdx.x * 128;
    const int tid = threadIdx.x;
    const int warp = tid >> 5, lane = tid & 31;
    const int wn = warp & 3;
    const int wm = warp >> 2;
    const int g = lane >> 2, tg = lane & 3;

    const uint32_t baseA = (uint32_t)__cvta_generic_to_shared(&smA[0][0]);
    const uint32_t baseB = (uint32_t)__cvta_generic_to_shared(&smB[0][0]);

    float acc[2][8][4];
#pragma unroll
    for (int i = 0; i < 2; i++)
#pragma unroll
        for (int j = 0; j < 8; j++)
#pragma unroll
            for (int q = 0; q < 4; q++) acc[i][j][q] = 0.f;

    // stage issuer
    const int lrow = tid >> 2, lk4 = (tid & 3) * 4;   // e = tid, tid+256
#define ISSUE(s, b)                                                                 \
    {                                                                               \
        _Pragma("unroll")                                                           \
        for (int it = 0; it < 2; it++) {                                            \
            int row = lrow + it * 64;                                               \
            int gn = n0 + row, gm = m0 + row;                                       \
            int okA = (gn < N_NODES) ? 16 : 0;                                      \
            int okB = (gm < N_NODES) ? 16 : 0;                                      \
            int cn = (gn < N_NODES) ? gn : (N_NODES - 1);                           \
            int cm = (gm < N_NODES) ? gm : (N_NODES - 1);                           \
            cp_async16(baseA + ((b) * 2560 + row * 20 + lk4) * 4,                   \
                       &g_U1[(long)cn * 128 + (s) * 16 + lk4], okA);                \
            cp_async16(baseB + ((b) * 2560 + row * 20 + lk4) * 4,                   \
                       &g_P [(long)cm * 128 + (s) * 16 + lk4], okB);                \
        }                                                                           \
        asm volatile("cp.async.commit_group;");                                     \
    }

    ISSUE(0, 0);
#pragma unroll
    for (int s = 0; s < 8; s++) {
        if (s < 7) ISSUE(s + 1, (s + 1) & 1);
        if (s < 7) { asm volatile("cp.async.wait_group 1;"); }
        else       { asm volatile("cp.async.wait_group 0;"); }
        __syncthreads();
        const float* sA = smA[s & 1];
        const float* sB = smB[s & 1];
#pragma unroll
        for (int ks = 0; ks < 2; ks++) {
            int k0 = ks * 8;
            uint32_t af[2][4];
#pragma unroll
            for (int i = 0; i < 2; i++) {
                int base = (wn * 32 + i * 16) * 20 + k0;
                af[i][0] = __float_as_uint(sA[base + g * 20 + tg]);
                af[i][1] = __float_as_uint(sA[base + (g + 8) * 20 + tg]);
                af[i][2] = __float_as_uint(sA[base + g * 20 + tg + 4]);
                af[i][3] = __float_as_uint(sA[base + (g + 8) * 20 + tg + 4]);
            }
            uint32_t bf[8][2];
#pragma unroll
            for (int j = 0; j < 8; j++) {
                int bb = (wm * 64 + j * 8 + g) * 20 + k0 + tg;
                bf[j][0] = __float_as_uint(sB[bb]);
                bf[j][1] = __float_as_uint(sB[bb + 4]);
            }
#pragma unroll
            for (int i = 0; i < 2; i++)
#pragma unroll
                for (int j = 0; j < 8; j++)
                    MMA_TF32(acc[i][j], af[i], bf[j]);
        }
        __syncthreads();
    }

    // epilogue: threshold + store
#pragma unroll
    for (int i = 0; i < 2; i++) {
#pragma unroll
        for (int j = 0; j < 8; j++) {
            int n = n0 + wn * 32 + i * 16 + g;
            int m = m0 + wm * 64 + j * 8 + 2 * tg;
            if (m < N_NODES) {
                float2 v0, v1;
                v0.x = (acc[i][j][0] >= DELTA_MIN) ? acc[i][j][0] : 0.f;
                v0.y = (acc[i][j][1] >= DELTA_MIN) ? acc[i][j][1] : 0.f;
                v1.x = (acc[i][j][2] >= DELTA_MIN) ? acc[i][j][2] : 0.f;
                v1.y = (acc[i][j][3] >= DELTA_MIN) ? acc[i][j][3] : 0.f;
                if (n < N_NODES)     *(float2*)&out[(long)n * N_NODES + m] = v0;
                if (n + 8 < N_NODES) *(float2*)&out[(long)(n + 8) * N_NODES + m] = v1;
            }
        }
    }
}

// ---------------- kernel 6: in-place row softmax (float4) -----------------
__global__ void k_softmax(float* __restrict__ out) {
    const int row = blockIdx.x;
    float* p = out + (long)row * N_NODES;
    const int tid = threadIdx.x;
    const bool act = tid < 250;
    __shared__ float redM[8];
    __shared__ float redS[8];

    float4 v0, v1;
    float mx = -1e30f;
    if (act) {
        v0 = *(const float4*)&p[tid * 8];
        v1 = *(const float4*)&p[tid * 8 + 4];
        mx = fmaxf(fmaxf(fmaxf(v0.x, v0.y), fmaxf(v0.z, v0.w)),
                   fmaxf(fmaxf(v1.x, v1.y), fmaxf(v1.z, v1.w)));
    }
#pragma unroll
    for (int o = 16; o; o >>= 1) mx = fmaxf(mx, __shfl_xor_sync(0xFFFFFFFFu, mx, o));
    if ((tid & 31) == 0) redM[tid >> 5] = mx;
    __syncthreads();
    float gmax = redM[0];
#pragma unroll
    for (int w = 1; w < 8; w++) gmax = fmaxf(gmax, redM[w]);

    float s = 0.f;
    if (act) {
        v0.x = __expf(v0.x - gmax); v0.y = __expf(v0.y - gmax);
        v0.z = __expf(v0.z - gmax); v0.w = __expf(v0.w - gmax);
        v1.x = __expf(v1.x - gmax); v1.y = __expf(v1.y - gmax);
        v1.z = __expf(v1.z - gmax); v1.w = __expf(v1.w - gmax);
        s = v0.x + v0.y + v0.z + v0.w + v1.x + v1.y + v1.z + v1.w;
    }
#pragma unroll
    for (int o = 16; o; o >>= 1) s += __shfl_xor_sync(0xFFFFFFFFu, s, o);
    if ((tid & 31) == 0) redS[tid >> 5] = s;
    __syncthreads();
    float tot = 0.f;
#pragma unroll
    for (int w = 0; w < 8; w++) tot += redS[w];
    float inv = 1.f / tot;
    if (act) {
        v0.x *= inv; v0.y *= inv; v0.z *= inv; v0.w *= inv;
        v1.x *= inv; v1.y *= inv; v1.z *= inv; v1.w *= inv;
        *(float4*)&p[tid * 8]     = v0;
        *(float4*)&p[tid * 8 + 4] = v1;
    }
}

// ---------------- launch ---------------------------------------------------
extern "C" void kernel_launch(void* const* d_in, const int* in_sizes, int n_in,
                              void* d_out, int out_size) {
    const float* tf   = (const float*)d_in[0];
    const float* li   = (const float*)d_in[1];
    const float* Ws1  = (const float*)d_in[2];
    const float* bs1  = (const float*)d_in[3];
    const float* Ws2  = (const float*)d_in[4];
    const float* bs2  = (const float*)d_in[5];
    const float* Wt1  = (const float*)d_in[6];
    const float* bt1  = (const float*)d_in[7];
    const float* Wt2  = (const float*)d_in[8];
    const float* bt2  = (const float*)d_in[9];
    const float* B    = (const float*)d_in[10];
    const int*   idxp = (const int*)d_in[11];
    const int*   tdp  = (const int*)d_in[12];
    float* out = (float*)d_out;

    k_hid_s  <<<dim3(8, 25), 256>>>(li, Ws1);
    k_hid_fin<<<128, 256>>>(tf, Wt1, bs1, bt1);
    k_embed  <<<500, 256>>>(Ws2, bs2, Wt2, bt2, idxp, tdp);
    k_u2b    <<<250, 256>>>(B);
    k_gemm   <<<dim3(16, 16), 256>>>(out);
    k_softmax<<<2000, 256>>>(out);
}

// round 5
// speedup vs baseline: 1.0661x; 1.0661x over previous
#include <cuda_runtime.h>
#include <math.h>
#include <stdint.h>

#define N_NODES 2000
#define NFEAT   128
#define LB      128
#define TFEAT   36
#define FC1     256
#define DELTA_MIN 0.05f

// ---------------- scratch (device globals; no allocation) ----------------
__device__ float g_accP[25][FC1 * LB];     // split-K partials, [split][t*256 + k]
__device__ float g_HsT[FC1 * LB];          // relu spatial hidden, [k][t]
__device__ float g_HtT[FC1 * LB];          // relu temporal hidden, [k][t]
__device__ float g_Wc[2][2 * N_NODES][FC1];// compacted gathered W2 cols [s][c'][k] (8.2MB)
__device__ float g_U1[N_NODES * LB];       // U[:,:,i1]  [n][t]  (tf32-rounded)
__device__ float g_U2[N_NODES * LB];       // U[:,:,i2]  [n][t]  (full fp32)
__device__ float g_P [N_NODES * LB];       // U2 @ B^T   [m][f]  (tf32-rounded)

__device__ __forceinline__ float to_tf32(float x) {
    uint32_t u;
    asm("cvt.rna.tf32.f32 %0, %1;" : "=r"(u) : "f"(x));
    return __uint_as_float(u);
}
__device__ __forceinline__ double pack2(float x, float y) {
    double d; asm("mov.b64 %0, {%1, %2};" : "=d"(d) : "f"(x), "f"(y)); return d;
}
__device__ __forceinline__ void fma2(double& acc, double a, double b) {
    asm("fma.rn.f32x2 %0, %1, %2, %0;" : "+d"(acc) : "d"(a), "d"(b));
}
__device__ __forceinline__ float2 unpack2(double d) {
    float2 r; asm("mov.b64 {%0, %1}, %2;" : "=f"(r.x), "=f"(r.y) : "d"(d)); return r;
}

// ---------------- kernel 1: spatial hidden, split-K, coalesced ------------
// grid (8 k-tiles of 32, 25 j-splits of 80), block 256
__global__ __launch_bounds__(256) void k_hid_s(const float* __restrict__ li,
                                               const float* __restrict__ Ws1) {
    __shared__ float smA[16 * 132];
    __shared__ float smW[16 * 36];
    const int k0 = blockIdx.x * 32;
    const int j0 = blockIdx.y * 80;
    const int tid = threadIdx.x;
    const int tx = tid & 7;
    const int ty = tid >> 3;

    float acc[4][4];
#pragma unroll
    for (int u = 0; u < 4; u++)
#pragma unroll
        for (int v = 0; v < 4; v++) acc[u][v] = 0.f;

    for (int jb = 0; jb < 80; jb += 16) {
        __syncthreads();
#pragma unroll
        for (int it = 0; it < 8; it++) {
            int e = tid + it * 256;
            int t = e >> 4, jj = e & 15;
            smA[jj * 132 + t] = li[t * N_NODES + j0 + jb + jj];
        }
#pragma unroll
        for (int it = 0; it < 2; it++) {
            int e = tid + it * 256;
            int jj = e >> 5, kk = e & 31;
            smW[jj * 36 + kk] = Ws1[(j0 + jb + jj) * FC1 + k0 + kk];
        }
        __syncthreads();
#pragma unroll
        for (int jj = 0; jj < 16; jj++) {
            float4 a = *(const float4*)&smA[jj * 132 + ty * 4];
            float4 w = *(const float4*)&smW[jj * 36 + tx * 4];
            float av[4] = {a.x, a.y, a.z, a.w};
            float wv[4] = {w.x, w.y, w.z, w.w};
#pragma unroll
            for (int u = 0; u < 4; u++)
#pragma unroll
                for (int v = 0; v < 4; v++) acc[u][v] += av[u] * wv[v];
        }
    }
    const int sp = blockIdx.y;
#pragma unroll
    for (int u = 0; u < 4; u++) {
        int t = ty * 4 + u;
        float4 v = make_float4(acc[u][0], acc[u][1], acc[u][2], acc[u][3]);
        *(float4*)&g_accP[sp][t * FC1 + k0 + tx * 4] = v;
    }
}

// ---------------- kernel 2: finalize spatial + temporal hidden ------------
__global__ void k_hid_fin(const float* __restrict__ tf, const float* __restrict__ Wt1,
                          const float* __restrict__ bs1, const float* __restrict__ bt1) {
    const int t = blockIdx.x;
    const int k = threadIdx.x;
    __shared__ float stf[TFEAT];
    if (k < TFEAT) stf[k] = tf[t * TFEAT + k];

    float hs = bs1[k];
#pragma unroll
    for (int s = 0; s < 25; s++) hs += g_accP[s][t * FC1 + k];
    g_HsT[k * 128 + t] = fmaxf(hs, 0.f);

    __syncthreads();
    float a = bt1[k];
#pragma unroll
    for (int j = 0; j < TFEAT; j++)
        a += stf[j] * Wt1[j * FC1 + k];
    g_HtT[k * 128 + t] = fmaxf(a, 0.f);
}

// ---------------- kernel 3a: pure gather of W2 columns --------------------
// grid 1000, block 256 (8 warps). warp -> one (tensor, c') pair; lanes over k.
__global__ __launch_bounds__(256) void k_gather(
    const float* __restrict__ Ws2, const float* __restrict__ Wt2,
    const int* __restrict__ idxp, const int* __restrict__ tdp) {

    const int idx = idxp[0];
    const int td  = tdp[0];
    const int i1  = (td >= 0) ? (idx - td) : idx;
    const int i2  = (td >= 0) ? idx        : (idx + td);

    const int gw   = blockIdx.x * 8 + (threadIdx.x >> 5);   // 0..7999
    const int lane = threadIdx.x & 31;
    const int s    = (gw >= 2 * N_NODES) ? 1 : 0;
    const int cp   = s ? (gw - 2 * N_NODES) : gw;           // 0..3999
    const int n    = cp >> 1;
    const long c   = (long)n * NFEAT + ((cp & 1) ? i2 : i1);
    const float* __restrict__ W = s ? Wt2 : Ws2;

    float v[8];
#pragma unroll
    for (int it = 0; it < 8; it++) {
        int k = lane + it * 32;
        v[it] = __ldg(&W[(long)k * (N_NODES * NFEAT) + c]);
    }
#pragma unroll
    for (int it = 0; it < 8; it++)
        g_Wc[s][cp][lane + it * 32] = v[it];
}

// ---------------- kernel 3b: embed compute -> U1, U2 ----------------------
// grid 500 (4 nodes = 8 c'), block 256 = (t 0..127) x (col-half h 0..1)
__global__ __launch_bounds__(256) void k_embed_c(
    const float* __restrict__ bs2, const float* __restrict__ bt2,
    const int* __restrict__ idxp, const int* __restrict__ tdp) {

    __shared__ float smWs[256 * 8];    // [k][cc]   8 KB
    __shared__ float smWt[256 * 8];    //           8 KB
    __shared__ float smHs[32 * 128];   // [kk][t]  16 KB
    __shared__ float smHt[32 * 128];   //          16 KB
    __shared__ float smBs[8], smBt[8];

    const int idx = idxp[0];
    const int td  = tdp[0];
    const int i1  = (td >= 0) ? (idx - td) : idx;
    const int i2  = (td >= 0) ? idx        : (idx + td);

    const int n0  = blockIdx.x * 4;
    const int tid = threadIdx.x;

    // stage compacted weights: coalesced reads from g_Wc
#pragma unroll
    for (int it = 0; it < 8; it++) {
        int e = tid + it * 256;
        int cc = e >> 8, k = e & 255;
        smWs[k * 8 + cc] = g_Wc[0][n0 * 2 + cc][k];
        smWt[k * 8 + cc] = g_Wc[1][n0 * 2 + cc][k];
    }
    if (tid < 8) {
        int c = (n0 + (tid >> 1)) * NFEAT + ((tid & 1) ? i2 : i1);
        smBs[tid] = bs2[c];
        smBt[tid] = bt2[c];
    }

    const int t = tid & 127;
    const int h = tid >> 7;    // cols h*4 .. h*4+3

    double accS01 = 0.0, accS23 = 0.0, accT01 = 0.0, accT23 = 0.0;

    for (int kc = 0; kc < 256; kc += 32) {
        __syncthreads();
#pragma unroll
        for (int it = 0; it < 4; it++) {
            int e4 = tid + it * 256;
            int kk = e4 >> 5, tt = (e4 & 31) * 4;
            *(float4*)&smHs[kk * 128 + tt] = *(const float4*)&g_HsT[(kc + kk) * 128 + tt];
            *(float4*)&smHt[kk * 128 + tt] = *(const float4*)&g_HtT[(kc + kk) * 128 + tt];
        }
        __syncthreads();
#pragma unroll 8
        for (int kk = 0; kk < 32; kk++) {
            float hs = smHs[kk * 128 + t];
            float ht = smHt[kk * 128 + t];
            double hh = pack2(hs, hs);
            double h2 = pack2(ht, ht);
            double2 ws = *(const double2*)&smWs[(kc + kk) * 8 + h * 4];
            double2 wt = *(const double2*)&smWt[(kc + kk) * 8 + h * 4];
            fma2(accS01, hh, ws.x);
            fma2(accS23, hh, ws.y);
            fma2(accT01, h2, wt.x);
            fma2(accT23, h2, wt.y);
        }
    }

    float2 s01 = unpack2(accS01), s23 = unpack2(accS23);
    float2 t01 = unpack2(accT01), t23 = unpack2(accT23);
    float sv[4] = {s01.x, s01.y, s23.x, s23.y};
    float tv[4] = {t01.x, t01.y, t23.x, t23.y};
#pragma unroll
    for (int q = 0; q < 4; q++) {
        int col = h * 4 + q;
        float v = fmaxf(sv[q] + smBs[col], 0.f) + fmaxf(tv[q] + smBt[col], 0.f);
        int n = n0 + (col >> 1);
        if (col & 1) g_U2[n * 128 + t] = v;            // fp32 -> P
        else         g_U1[n * 128 + t] = to_tf32(v);   // tf32 -> mma A
    }
}

// ---------------- kernel 4: P = U2 @ B^T ----------------------------------
// grid 250 (8 rows each), block 256 = (f 0..127) x (row-half rh 0..1)
__global__ __launch_bounds__(256) void k_u2b(const float* __restrict__ B) {
    __shared__ float smB[128 * 36];
    __shared__ float smU[8 * 128];
    const int m0  = blockIdx.x * 8;
    const int tid = threadIdx.x;
    const int f   = tid & 127;
    const int rh  = tid >> 7;

    {
        int r = tid >> 5, t4 = (tid & 31) * 4;
        *(float4*)&smU[r * 128 + t4] = *(const float4*)&g_U2[(m0 + r) * 128 + t4];
    }

    float acc[4];
#pragma unroll
    for (int q = 0; q < 4; q++) acc[q] = 0.f;

    for (int gc = 0; gc < 128; gc += 32) {
        __syncthreads();
#pragma unroll
        for (int it = 0; it < 4; it++) {
            int e = tid + it * 256;
            int fr = e >> 3, g4 = (e & 7) * 4;
            *(float4*)&smB[fr * 36 + g4] = *(const float4*)&B[fr * 128 + gc + g4];
        }
        __syncthreads();
#pragma unroll
        for (int gi = 0; gi < 8; gi++) {
            float4 b = *(const float4*)&smB[f * 36 + gi * 4];
#pragma unroll
            for (int rr = 0; rr < 4; rr++) {
                float4 u = *(const float4*)&smU[(rh * 4 + rr) * 128 + gc + gi * 4];
                acc[rr] += u.x * b.x + u.y * b.y + u.z * b.z + u.w * b.w;
            }
        }
    }
#pragma unroll
    for (int rr = 0; rr < 4; rr++)
        g_P[(m0 + rh * 4 + rr) * 128 + f] = to_tf32(acc[rr]);
}

// ---------------- kernel 5: x = U1 @ P^T (tf32 tensor cores, R3 version) --
#define MMA_TF32(c, a, b)                                                          \
    asm volatile("mma.sync.aligned.m16n8k8.row.col.f32.tf32.tf32.f32 "             \
                 "{%0,%1,%2,%3},{%4,%5,%6,%7},{%8,%9},{%0,%1,%2,%3};"              \
                 : "+f"(c[0]), "+f"(c[1]), "+f"(c[2]), "+f"(c[3])                  \
                 : "r"(a[0]), "r"(a[1]), "r"(a[2]), "r"(a[3]), "r"(b[0]), "r"(b[1]))

__global__ __launch_bounds__(256) void k_gemm(float* __restrict__ out) {
    __shared__ float smA[128 * 36];
    __shared__ float smB[128 * 36];
    const int n0 = blockIdx.y * 128;
    const int m0 = blockIdx.x * 128;
    const int tid = threadIdx.x;
    const int warp = tid >> 5, lane = tid & 31;
    const int wn = warp & 3;
    const int wm = warp >> 2;
    const int g = lane >> 2, tg = lane & 3;
    const int lrow = tid >> 3, lkk = (tid & 7) * 4;

    float acc[2][8][4];
#pragma unroll
    for (int i = 0; i < 2; i++)
#pragma unroll
        for (int j = 0; j < 8; j++)
#pragma unroll
            for (int q = 0; q < 4; q++) acc[i][j][q] = 0.f;

    float4 ra[4], rb[4];
#pragma unroll
    for (int it = 0; it < 4; it++) {
        int row = lrow + it * 32;
        ra[it] = (n0 + row < N_NODES) ? *(const float4*)&g_U1[(n0 + row) * 128 + lkk]
                                      : make_float4(0, 0, 0, 0);
        rb[it] = (m0 + row < N_NODES) ? *(const float4*)&g_P [(m0 + row) * 128 + lkk]
                                      : make_float4(0, 0, 0, 0);
    }

    for (int kc = 0; kc < 4; kc++) {
        __syncthreads();
#pragma unroll
        for (int it = 0; it < 4; it++) {
            int row = lrow + it * 32;
            *(float4*)&smA[row * 36 + lkk] = ra[it];
            *(float4*)&smB[row * 36 + lkk] = rb[it];
        }
        __syncthreads();
        if (kc < 3) {
            int kn = (kc + 1) * 32;
#pragma unroll
            for (int it = 0; it < 4; it++) {
                int row = lrow + it * 32;
                ra[it] = (n0 + row < N_NODES) ? *(const float4*)&g_U1[(n0 + row) * 128 + kn + lkk]
                                              : make_float4(0, 0, 0, 0);
                rb[it] = (m0 + row < N_NODES) ? *(const float4*)&g_P [(m0 + row) * 128 + kn + lkk]
                                              : make_float4(0, 0, 0, 0);
            }
        }
#pragma unroll
        for (int ks = 0; ks < 4; ks++) {
            int k0 = ks * 8;
            uint32_t af[2][4];
#pragma unroll
            for (int i = 0; i < 2; i++) {
                int base = (wn * 32 + i * 16) * 36 + k0;
                af[i][0] = __float_as_uint(smA[base + g * 36 + tg]);
                af[i][1] = __float_as_uint(smA[base + (g + 8) * 36 + tg]);
                af[i][2] = __float_as_uint(smA[base + g * 36 + tg + 4]);
                af[i][3] = __float_as_uint(smA[base + (g + 8) * 36 + tg + 4]);
            }
            uint32_t bf[8][2];
#pragma unroll
            for (int j = 0; j < 8; j++) {
                int bb = (wm * 64 + j * 8 + g) * 36 + k0 + tg;
                bf[j][0] = __float_as_uint(smB[bb]);
                bf[j][1] = __float_as_uint(smB[bb + 4]);
            }
#pragma unroll
            for (int i = 0; i < 2; i++)
#pragma unroll
                for (int j = 0; j < 8; j++)
                    MMA_TF32(acc[i][j], af[i], bf[j]);
        }
    }

#pragma unroll
    for (int i = 0; i < 2; i++) {
#pragma unroll
        for (int j = 0; j < 8; j++) {
            int n = n0 + wn * 32 + i * 16 + g;
            int m = m0 + wm * 64 + j * 8 + 2 * tg;
            if (m < N_NODES) {
                float2 v0, v1;
                v0.x = (acc[i][j][0] >= DELTA_MIN) ? acc[i][j][0] : 0.f;
                v0.y = (acc[i][j][1] >= DELTA_MIN) ? acc[i][j][1] : 0.f;
                v1.x = (acc[i][j][2] >= DELTA_MIN) ? acc[i][j][2] : 0.f;
                v1.y = (acc[i][j][3] >= DELTA_MIN) ? acc[i][j][3] : 0.f;
                if (n < N_NODES)     *(float2*)&out[(long)n * N_NODES + m] = v0;
                if (n + 8 < N_NODES) *(float2*)&out[(long)(n + 8) * N_NODES + m] = v1;
            }
        }
    }
}

// ---------------- kernel 6: in-place row softmax (float4) -----------------
__global__ void k_softmax(float* __restrict__ out) {
    const int row = blockIdx.x;
    float* p = out + (long)row * N_NODES;
    const int tid = threadIdx.x;
    const bool act = tid < 250;
    __shared__ float redM[8];
    __shared__ float redS[8];

    float4 v0, v1;
    float mx = -1e30f;
    if (act) {
        v0 = *(const float4*)&p[tid * 8];
        v1 = *(const float4*)&p[tid * 8 + 4];
        mx = fmaxf(fmaxf(fmaxf(v0.x, v0.y), fmaxf(v0.z, v0.w)),
                   fmaxf(fmaxf(v1.x, v1.y), fmaxf(v1.z, v1.w)));
    }
#pragma unroll
    for (int o = 16; o; o >>= 1) mx = fmaxf(mx, __shfl_xor_sync(0xFFFFFFFFu, mx, o));
    if ((tid & 31) == 0) redM[tid >> 5] = mx;
    __syncthreads();
    float gmax = redM[0];
#pragma unroll
    for (int w = 1; w < 8; w++) gmax = fmaxf(gmax, redM[w]);

    float s = 0.f;
    if (act) {
        v0.x = __expf(v0.x - gmax); v0.y = __expf(v0.y - gmax);
        v0.z = __expf(v0.z - gmax); v0.w = __expf(v0.w - gmax);
        v1.x = __expf(v1.x - gmax); v1.y = __expf(v1.y - gmax);
        v1.z = __expf(v1.z - gmax); v1.w = __expf(v1.w - gmax);
        s = v0.x + v0.y + v0.z + v0.w + v1.x + v1.y + v1.z + v1.w;
    }
#pragma unroll
    for (int o = 16; o; o >>= 1) s += __shfl_xor_sync(0xFFFFFFFFu, s, o);
    if ((tid & 31) == 0) redS[tid >> 5] = s;
    __syncthreads();
    float tot = 0.f;
#pragma unroll
    for (int w = 0; w < 8; w++) tot += redS[w];
    float inv = 1.f / tot;
    if (act) {
        v0.x *= inv; v0.y *= inv; v0.z *= inv; v0.w *= inv;
        v1.x *= inv; v1.y *= inv; v1.z *= inv; v1.w *= inv;
        *(float4*)&p[tid * 8]     = v0;
        *(float4*)&p[tid * 8 + 4] = v1;
    }
}

// ---------------- launch ---------------------------------------------------
extern "C" void kernel_launch(void* const* d_in, const int* in_sizes, int n_in,
                              void* d_out, int out_size) {
    const float* tf   = (const float*)d_in[0];
    const float* li   = (const float*)d_in[1];
    const float* Ws1  = (const float*)d_in[2];
    const float* bs1  = (const float*)d_in[3];
    const float* Ws2  = (const float*)d_in[4];
    const float* bs2  = (const float*)d_in[5];
    const float* Wt1  = (const float*)d_in[6];
    const float* bt1  = (const float*)d_in[7];
    const float* Wt2  = (const float*)d_in[8];
    const float* bt2  = (const float*)d_in[9];
    const float* B    = (const float*)d_in[10];
    const int*   idxp = (const int*)d_in[11];
    const int*   tdp  = (const int*)d_in[12];
    float* out = (float*)d_out;

    k_gather <<<1000, 256>>>(Ws2, Wt2, idxp, tdp);
    k_hid_s  <<<dim3(8, 25), 256>>>(li, Ws1);
    k_hid_fin<<<128, 256>>>(tf, Wt1, bs1, bt1);
    k_embed_c<<<500, 256>>>(bs2, bt2, idxp, tdp);
    k_u2b    <<<250, 256>>>(B);
    k_gemm   <<<dim3(16, 16), 256>>>(out);
    k_softmax<<<2000, 256>>>(out);
}

// round 6
// speedup vs baseline: 1.2393x; 1.1625x over previous
#include <cuda_runtime.h>
#include <math.h>
#include <stdint.h>

#define N_NODES 2000
#define NFEAT   128
#define LB      128
#define TFEAT   36
#define FC1     256
#define DELTA_MIN 0.05f

// ---------------- scratch (device globals; no allocation) ----------------
__device__ float g_accP[25][FC1 * LB];     // split-K partials, [split][t*256 + k]
__device__ float g_Hs[LB * FC1];           // relu spatial hidden, [t][k] (tf32)
__device__ float g_Ht[LB * FC1];           // relu temporal hidden, [t][k] (tf32)
__device__ float g_Wc[2][2 * N_NODES][FC1];// compacted gathered W2 cols [s][c'][k] (tf32)
__device__ float g_U1[N_NODES * LB];       // U[:,:,i1]  [n][t]  (tf32)
__device__ float g_U2[N_NODES * LB];       // U[:,:,i2]  [n][t]  (tf32)
__device__ float g_P [N_NODES * LB];       // U2 @ B^T   [m][f]  (tf32)

__device__ __forceinline__ float to_tf32(float x) {
    uint32_t u;
    asm("cvt.rna.tf32.f32 %0, %1;" : "=r"(u) : "f"(x));
    return __uint_as_float(u);
}

#define MMA_TF32(c, a, b)                                                          \
    asm volatile("mma.sync.aligned.m16n8k8.row.col.f32.tf32.tf32.f32 "             \
                 "{%0,%1,%2,%3},{%4,%5,%6,%7},{%8,%9},{%0,%1,%2,%3};"              \
                 : "+f"(c[0]), "+f"(c[1]), "+f"(c[2]), "+f"(c[3])                  \
                 : "r"(a[0]), "r"(a[1]), "r"(a[2]), "r"(a[3]), "r"(b[0]), "r"(b[1]))

// ---------------- kernel 1: spatial hidden, split-K, coalesced ------------
// grid (8 k-tiles of 32, 25 j-splits of 80), block 256
__global__ __launch_bounds__(256) void k_hid_s(const float* __restrict__ li,
                                               const float* __restrict__ Ws1) {
    __shared__ float smA[16 * 132];
    __shared__ float smW[16 * 36];
    const int k0 = blockIdx.x * 32;
    const int j0 = blockIdx.y * 80;
    const int tid = threadIdx.x;
    const int tx = tid & 7;
    const int ty = tid >> 3;

    float acc[4][4];
#pragma unroll
    for (int u = 0; u < 4; u++)
#pragma unroll
        for (int v = 0; v < 4; v++) acc[u][v] = 0.f;

    for (int jb = 0; jb < 80; jb += 16) {
        __syncthreads();
#pragma unroll
        for (int it = 0; it < 8; it++) {
            int e = tid + it * 256;
            int t = e >> 4, jj = e & 15;
            smA[jj * 132 + t] = li[t * N_NODES + j0 + jb + jj];
        }
#pragma unroll
        for (int it = 0; it < 2; it++) {
            int e = tid + it * 256;
            int jj = e >> 5, kk = e & 31;
            smW[jj * 36 + kk] = Ws1[(j0 + jb + jj) * FC1 + k0 + kk];
        }
        __syncthreads();
#pragma unroll
        for (int jj = 0; jj < 16; jj++) {
            float4 a = *(const float4*)&smA[jj * 132 + ty * 4];
            float4 w = *(const float4*)&smW[jj * 36 + tx * 4];
            float av[4] = {a.x, a.y, a.z, a.w};
            float wv[4] = {w.x, w.y, w.z, w.w};
#pragma unroll
            for (int u = 0; u < 4; u++)
#pragma unroll
                for (int v = 0; v < 4; v++) acc[u][v] += av[u] * wv[v];
        }
    }
    const int sp = blockIdx.y;
#pragma unroll
    for (int u = 0; u < 4; u++) {
        int t = ty * 4 + u;
        float4 v = make_float4(acc[u][0], acc[u][1], acc[u][2], acc[u][3]);
        *(float4*)&g_accP[sp][t * FC1 + k0 + tx * 4] = v;
    }
}

// ---------------- kernel 2: finalize hidden, store [t][k] tf32 ------------
// grid 128 (t), block 256 (k)
__global__ void k_hid_fin(const float* __restrict__ tf, const float* __restrict__ Wt1,
                          const float* __restrict__ bs1, const float* __restrict__ bt1) {
    const int t = blockIdx.x;
    const int k = threadIdx.x;
    __shared__ float stf[TFEAT];
    if (k < TFEAT) stf[k] = tf[t * TFEAT + k];

    float hs = bs1[k];
#pragma unroll
    for (int s = 0; s < 25; s++) hs += g_accP[s][t * FC1 + k];
    g_Hs[t * FC1 + k] = to_tf32(fmaxf(hs, 0.f));

    __syncthreads();
    float a = bt1[k];
#pragma unroll
    for (int j = 0; j < TFEAT; j++)
        a += stf[j] * Wt1[j * FC1 + k];
    g_Ht[t * FC1 + k] = to_tf32(fmaxf(a, 0.f));
}

// ---------------- kernel 3a: pure gather of W2 columns (tf32) -------------
// grid 1000, block 256 (8 warps). warp -> one (tensor, c') pair; lanes over k.
__global__ __launch_bounds__(256) void k_gather(
    const float* __restrict__ Ws2, const float* __restrict__ Wt2,
    const int* __restrict__ idxp, const int* __restrict__ tdp) {

    const int idx = idxp[0];
    const int td  = tdp[0];
    const int i1  = (td >= 0) ? (idx - td) : idx;
    const int i2  = (td >= 0) ? idx        : (idx + td);

    const int gw   = blockIdx.x * 8 + (threadIdx.x >> 5);   // 0..7999
    const int lane = threadIdx.x & 31;
    const int s    = (gw >= 2 * N_NODES) ? 1 : 0;
    const int cp   = s ? (gw - 2 * N_NODES) : gw;           // 0..3999
    const int n    = cp >> 1;
    const long c   = (long)n * NFEAT + ((cp & 1) ? i2 : i1);
    const float* __restrict__ W = s ? Wt2 : Ws2;

    float v[8];
#pragma unroll
    for (int it = 0; it < 8; it++) {
        int k = lane + it * 32;
        v[it] = __ldg(&W[(long)k * (N_NODES * NFEAT) + c]);
    }
#pragma unroll
    for (int it = 0; it < 8; it++)
        g_Wc[s][cp][lane + it * 32] = to_tf32(v[it]);
}

// ---------------- kernel 3b: embed via tf32 mma -> U1, U2 -----------------
// grid 63 (64 c' each), block 256 (8 warps: 4 t-strips x 2 c-strips)
// accS[t][c] = sum_k Hs[t][k] * Wc[0][c][k]; accT likewise. Then relu+bias+sum.
__global__ __launch_bounds__(256) void k_embed(
    const float* __restrict__ bs2, const float* __restrict__ bt2,
    const int* __restrict__ idxp, const int* __restrict__ tdp) {

    __shared__ float smH[2][128 * 36];   // [s][t][k-chunk 32] pad 36 : 36 KB
    __shared__ float smW[2][64 * 36];    // [s][cc][k-chunk 32]       : 18 KB
    __shared__ float smBs[64], smBt[64];

    const int idx = idxp[0];
    const int td  = tdp[0];
    const int i1  = (td >= 0) ? (idx - td) : idx;
    const int i2  = (td >= 0) ? idx        : (idx + td);

    const int c0  = blockIdx.x * 64;
    const int tid = threadIdx.x;
    const int warp = tid >> 5, lane = tid & 31;
    const int wt = warp & 3;          // t-strip of 32
    const int wc = warp >> 2;         // c-strip of 32
    const int g = lane >> 2, tg = lane & 3;

    if (tid < 64) {
        int cp = c0 + tid;
        float b1 = 0.f, b2 = 0.f;
        if (cp < 2 * N_NODES) {
            int c = (cp >> 1) * NFEAT + ((cp & 1) ? i2 : i1);
            b1 = bs2[c]; b2 = bt2[c];
        }
        smBs[tid] = b1; smBt[tid] = b2;
    }

    float accS[2][4][4], accT[2][4][4];
#pragma unroll
    for (int i = 0; i < 2; i++)
#pragma unroll
        for (int j = 0; j < 4; j++)
#pragma unroll
            for (int q = 0; q < 4; q++) { accS[i][j][q] = 0.f; accT[i][j][q] = 0.f; }

    for (int kc = 0; kc < FC1; kc += 32) {
        __syncthreads();
        // stage H chunks: 128 t x 32 k, both tensors
#pragma unroll
        for (int it = 0; it < 4; it++) {
            int e = tid + it * 256;
            int t = e >> 3, k4 = (e & 7) * 4;
            *(float4*)&smH[0][t * 36 + k4] = *(const float4*)&g_Hs[t * FC1 + kc + k4];
            *(float4*)&smH[1][t * 36 + k4] = *(const float4*)&g_Ht[t * FC1 + kc + k4];
        }
        // stage W chunks: 64 c x 32 k, both tensors
#pragma unroll
        for (int it = 0; it < 2; it++) {
            int e = tid + it * 256;
            int cc = e >> 3, k4 = (e & 7) * 4;
            int cp = c0 + cc; if (cp >= 2 * N_NODES) cp = 2 * N_NODES - 1;
            *(float4*)&smW[0][cc * 36 + k4] = *(const float4*)&g_Wc[0][cp][kc + k4];
            *(float4*)&smW[1][cc * 36 + k4] = *(const float4*)&g_Wc[1][cp][kc + k4];
        }
        __syncthreads();
#pragma unroll
        for (int ks = 0; ks < 4; ks++) {
            int k0 = ks * 8;
            uint32_t aS[2][4], aT[2][4];
#pragma unroll
            for (int i = 0; i < 2; i++) {
                int base = (wt * 32 + i * 16) * 36 + k0;
                aS[i][0] = __float_as_uint(smH[0][base + g * 36 + tg]);
                aS[i][1] = __float_as_uint(smH[0][base + (g + 8) * 36 + tg]);
                aS[i][2] = __float_as_uint(smH[0][base + g * 36 + tg + 4]);
                aS[i][3] = __float_as_uint(smH[0][base + (g + 8) * 36 + tg + 4]);
                aT[i][0] = __float_as_uint(smH[1][base + g * 36 + tg]);
                aT[i][1] = __float_as_uint(smH[1][base + (g + 8) * 36 + tg]);
                aT[i][2] = __float_as_uint(smH[1][base + g * 36 + tg + 4]);
                aT[i][3] = __float_as_uint(smH[1][base + (g + 8) * 36 + tg + 4]);
            }
            uint32_t bS[4][2], bT[4][2];
#pragma unroll
            for (int j = 0; j < 4; j++) {
                int bb = (wc * 32 + j * 8 + g) * 36 + k0 + tg;
                bS[j][0] = __float_as_uint(smW[0][bb]);
                bS[j][1] = __float_as_uint(smW[0][bb + 4]);
                bT[j][0] = __float_as_uint(smW[1][bb]);
                bT[j][1] = __float_as_uint(smW[1][bb + 4]);
            }
#pragma unroll
            for (int i = 0; i < 2; i++)
#pragma unroll
                for (int j = 0; j < 4; j++) {
                    MMA_TF32(accS[i][j], aS[i], bS[j]);
                    MMA_TF32(accT[i][j], aT[i], bT[j]);
                }
        }
    }

    // epilogue: relu(s+bs) + relu(t+bt), scatter to U1/U2 by parity of c'
#pragma unroll
    for (int i = 0; i < 2; i++)
#pragma unroll
        for (int j = 0; j < 4; j++)
#pragma unroll
            for (int q = 0; q < 4; q++) {
                int t   = wt * 32 + i * 16 + g + ((q & 2) ? 8 : 0);
                int col = wc * 32 + j * 8 + 2 * tg + (q & 1);
                int cp  = c0 + col;
                if (cp < 2 * N_NODES) {
                    float v = fmaxf(accS[i][j][q] + smBs[col], 0.f)
                            + fmaxf(accT[i][j][q] + smBt[col], 0.f);
                    int n = cp >> 1;
                    if (cp & 1) g_U2[n * 128 + t] = to_tf32(v);
                    else        g_U1[n * 128 + t] = to_tf32(v);
                }
            }
}

// ---------------- kernel 4: P = U2 @ B^T via tf32 mma ---------------------
// grid 16 (m-tiles 128), block 256 (8 warps: 4 m-strips x 2 f-strips of 64)
__global__ __launch_bounds__(256) void k_u2b(const float* __restrict__ B) {
    __shared__ float smA[128 * 36];   // [m][g-chunk 32]
    __shared__ float smB[128 * 36];   // [f][g-chunk 32]
    const int m0  = blockIdx.x * 128;
    const int tid = threadIdx.x;
    const int warp = tid >> 5, lane = tid & 31;
    const int wm = warp & 3;          // m-strip of 32
    const int wf = warp >> 2;         // f-strip of 64
    const int g = lane >> 2, tg = lane & 3;

    float acc[2][8][4];
#pragma unroll
    for (int i = 0; i < 2; i++)
#pragma unroll
        for (int j = 0; j < 8; j++)
#pragma unroll
            for (int q = 0; q < 4; q++) acc[i][j][q] = 0.f;

    for (int gc = 0; gc < 128; gc += 32) {
        __syncthreads();
#pragma unroll
        for (int it = 0; it < 4; it++) {
            int e = tid + it * 256;
            int row = e >> 3, k4 = (e & 7) * 4;
            int m = m0 + row; if (m >= N_NODES) m = N_NODES - 1;
            *(float4*)&smA[row * 36 + k4] = *(const float4*)&g_U2[m * 128 + gc + k4];
            float4 b = *(const float4*)&B[row * 128 + gc + k4];
            b.x = to_tf32(b.x); b.y = to_tf32(b.y); b.z = to_tf32(b.z); b.w = to_tf32(b.w);
            *(float4*)&smB[row * 36 + k4] = b;
        }
        __syncthreads();
#pragma unroll
        for (int ks = 0; ks < 4; ks++) {
            int k0 = ks * 8;
            uint32_t af[2][4];
#pragma unroll
            for (int i = 0; i < 2; i++) {
                int base = (wm * 32 + i * 16) * 36 + k0;
                af[i][0] = __float_as_uint(smA[base + g * 36 + tg]);
                af[i][1] = __float_as_uint(smA[base + (g + 8) * 36 + tg]);
                af[i][2] = __float_as_uint(smA[base + g * 36 + tg + 4]);
                af[i][3] = __float_as_uint(smA[base + (g + 8) * 36 + tg + 4]);
            }
            uint32_t bf[8][2];
#pragma unroll
            for (int j = 0; j < 8; j++) {
                int bb = (wf * 64 + j * 8 + g) * 36 + k0 + tg;
                bf[j][0] = __float_as_uint(smB[bb]);
                bf[j][1] = __float_as_uint(smB[bb + 4]);
            }
#pragma unroll
            for (int i = 0; i < 2; i++)
#pragma unroll
                for (int j = 0; j < 8; j++)
                    MMA_TF32(acc[i][j], af[i], bf[j]);
        }
    }

#pragma unroll
    for (int i = 0; i < 2; i++)
#pragma unroll
        for (int j = 0; j < 8; j++) {
            int m = m0 + wm * 32 + i * 16 + g;
            int f = wf * 64 + j * 8 + 2 * tg;
            if (m < N_NODES) {
                float2 v0 = make_float2(to_tf32(acc[i][j][0]), to_tf32(acc[i][j][1]));
                *(float2*)&g_P[m * 128 + f] = v0;
            }
            if (m + 8 < N_NODES) {
                float2 v1 = make_float2(to_tf32(acc[i][j][2]), to_tf32(acc[i][j][3]));
                *(float2*)&g_P[(m + 8) * 128 + f] = v1;
            }
        }
}

// ---------------- kernel 5: x = U1 @ P^T (tf32 tensor cores) --------------
__global__ __launch_bounds__(256) void k_gemm(float* __restrict__ out) {
    __shared__ float smA[128 * 36];
    __shared__ float smB[128 * 36];
    const int n0 = blockIdx.y * 128;
    const int m0 = blockIdx.x * 128;
    const int tid = threadIdx.x;
    const int warp = tid >> 5, lane = tid & 31;
    const int wn = warp & 3;
    const int wm = warp >> 2;
    const int g = lane >> 2, tg = lane & 3;
    const int lrow = tid >> 3, lkk = (tid & 7) * 4;

    float acc[2][8][4];
#pragma unroll
    for (int i = 0; i < 2; i++)
#pragma unroll
        for (int j = 0; j < 8; j++)
#pragma unroll
            for (int q = 0; q < 4; q++) acc[i][j][q] = 0.f;

    float4 ra[4], rb[4];
#pragma unroll
    for (int it = 0; it < 4; it++) {
        int row = lrow + it * 32;
        ra[it] = (n0 + row < N_NODES) ? *(const float4*)&g_U1[(n0 + row) * 128 + lkk]
                                      : make_float4(0, 0, 0, 0);
        rb[it] = (m0 + row < N_NODES) ? *(const float4*)&g_P [(m0 + row) * 128 + lkk]
                                      : make_float4(0, 0, 0, 0);
    }

    for (int kc = 0; kc < 4; kc++) {
        __syncthreads();
#pragma unroll
        for (int it = 0; it < 4; it++) {
            int row = lrow + it * 32;
            *(float4*)&smA[row * 36 + lkk] = ra[it];
            *(float4*)&smB[row * 36 + lkk] = rb[it];
        }
        __syncthreads();
        if (kc < 3) {
            int kn = (kc + 1) * 32;
#pragma unroll
            for (int it = 0; it < 4; it++) {
                int row = lrow + it * 32;
                ra[it] = (n0 + row < N_NODES) ? *(const float4*)&g_U1[(n0 + row) * 128 + kn + lkk]
                                              : make_float4(0, 0, 0, 0);
                rb[it] = (m0 + row < N_NODES) ? *(const float4*)&g_P [(m0 + row) * 128 + kn + lkk]
                                              : make_float4(0, 0, 0, 0);
            }
        }
#pragma unroll
        for (int ks = 0; ks < 4; ks++) {
            int k0 = ks * 8;
            uint32_t af[2][4];
#pragma unroll
            for (int i = 0; i < 2; i++) {
                int base = (wn * 32 + i * 16) * 36 + k0;
                af[i][0] = __float_as_uint(smA[base + g * 36 + tg]);
                af[i][1] = __float_as_uint(smA[base + (g + 8) * 36 + tg]);
                af[i][2] = __float_as_uint(smA[base + g * 36 + tg + 4]);
                af[i][3] = __float_as_uint(smA[base + (g + 8) * 36 + tg + 4]);
            }
            uint32_t bf[8][2];
#pragma unroll
            for (int j = 0; j < 8; j++) {
                int bb = (wm * 64 + j * 8 + g) * 36 + k0 + tg;
                bf[j][0] = __float_as_uint(smB[bb]);
                bf[j][1] = __float_as_uint(smB[bb + 4]);
            }
#pragma unroll
            for (int i = 0; i < 2; i++)
#pragma unroll
                for (int j = 0; j < 8; j++)
                    MMA_TF32(acc[i][j], af[i], bf[j]);
        }
    }

#pragma unroll
    for (int i = 0; i < 2; i++) {
#pragma unroll
        for (int j = 0; j < 8; j++) {
            int n = n0 + wn * 32 + i * 16 + g;
            int m = m0 + wm * 64 + j * 8 + 2 * tg;
            if (m < N_NODES) {
                float2 v0, v1;
                v0.x = (acc[i][j][0] >= DELTA_MIN) ? acc[i][j][0] : 0.f;
                v0.y = (acc[i][j][1] >= DELTA_MIN) ? acc[i][j][1] : 0.f;
                v1.x = (acc[i][j][2] >= DELTA_MIN) ? acc[i][j][2] : 0.f;
                v1.y = (acc[i][j][3] >= DELTA_MIN) ? acc[i][j][3] : 0.f;
                if (n < N_NODES)     *(float2*)&out[(long)n * N_NODES + m] = v0;
                if (n + 8 < N_NODES) *(float2*)&out[(long)(n + 8) * N_NODES + m] = v1;
            }
        }
    }
}

// ---------------- kernel 6: in-place row softmax (float4) -----------------
__global__ void k_softmax(float* __restrict__ out) {
    const int row = blockIdx.x;
    float* p = out + (long)row * N_NODES;
    const int tid = threadIdx.x;
    const bool act = tid < 250;
    __shared__ float redM[8];
    __shared__ float redS[8];

    float4 v0, v1;
    float mx = -1e30f;
    if (act) {
        v0 = *(const float4*)&p[tid * 8];
        v1 = *(const float4*)&p[tid * 8 + 4];
        mx = fmaxf(fmaxf(fmaxf(v0.x, v0.y), fmaxf(v0.z, v0.w)),
                   fmaxf(fmaxf(v1.x, v1.y), fmaxf(v1.z, v1.w)));
    }
#pragma unroll
    for (int o = 16; o; o >>= 1) mx = fmaxf(mx, __shfl_xor_sync(0xFFFFFFFFu, mx, o));
    if ((tid & 31) == 0) redM[tid >> 5] = mx;
    __syncthreads();
    float gmax = redM[0];
#pragma unroll
    for (int w = 1; w < 8; w++) gmax = fmaxf(gmax, redM[w]);

    float s = 0.f;
    if (act) {
        v0.x = __expf(v0.x - gmax); v0.y = __expf(v0.y - gmax);
        v0.z = __expf(v0.z - gmax); v0.w = __expf(v0.w - gmax);
        v1.x = __expf(v1.x - gmax); v1.y = __expf(v1.y - gmax);
        v1.z = __expf(v1.z - gmax); v1.w = __expf(v1.w - gmax);
        s = v0.x + v0.y + v0.z + v0.w + v1.x + v1.y + v1.z + v1.w;
    }
#pragma unroll
    for (int o = 16; o; o >>= 1) s += __shfl_xor_sync(0xFFFFFFFFu, s, o);
    if ((tid & 31) == 0) redS[tid >> 5] = s;
    __syncthreads();
    float tot = 0.f;
#pragma unroll
    for (int w = 0; w < 8; w++) tot += redS[w];
    float inv = 1.f / tot;
    if (act) {
        v0.x *= inv; v0.y *= inv; v0.z *= inv; v0.w *= inv;
        v1.x *= inv; v1.y *= inv; v1.z *= inv; v1.w *= inv;
        *(float4*)&p[tid * 8]     = v0;
        *(float4*)&p[tid * 8 + 4] = v1;
    }
}

// ---------------- launch ---------------------------------------------------
extern "C" void kernel_launch(void* const* d_in, const int* in_sizes, int n_in,
                              void* d_out, int out_size) {
    const float* tf   = (const float*)d_in[0];
    const float* li   = (const float*)d_in[1];
    const float* Ws1  = (const float*)d_in[2];
    const float* bs1  = (const float*)d_in[3];
    const float* Ws2  = (const float*)d_in[4];
    const float* bs2  = (const float*)d_in[5];
    const float* Wt1  = (const float*)d_in[6];
    const float* bt1  = (const float*)d_in[7];
    const float* Wt2  = (const float*)d_in[8];
    const float* bt2  = (const float*)d_in[9];
    const float* B    = (const float*)d_in[10];
    const int*   idxp = (const int*)d_in[11];
    const int*   tdp  = (const int*)d_in[12];
    float* out = (float*)d_out;

    k_gather <<<1000, 256>>>(Ws2, Wt2, idxp, tdp);
    k_hid_s  <<<dim3(8, 25), 256>>>(li, Ws1);
    k_hid_fin<<<128, 256>>>(tf, Wt1, bs1, bt1);
    k_embed  <<<63, 256>>>(bs2, bt2, idxp, tdp);
    k_u2b    <<<16, 256>>>(B);
    k_gemm   <<<dim3(16, 16), 256>>>(out);
    k_softmax<<<2000, 256>>>(out);
}

// round 7
// speedup vs baseline: 1.2491x; 1.0079x over previous
#include <cuda_runtime.h>
#include <math.h>
#include <stdint.h>

#define N_NODES 2000
#define NFEAT   128
#define LB      128
#define TFEAT   36
#define FC1     256
#define DELTA_MIN 0.05f

// ---------------- scratch (device globals; no allocation) ----------------
__device__ float g_accP[25][FC1 * LB];     // split-K partials, [split][t*256 + k]
__device__ float g_Hs[LB * FC1];           // relu spatial hidden, [t][k] (tf32)
__device__ float g_Ht[LB * FC1];           // relu temporal hidden, [t][k] (tf32)
__device__ float g_Wc[2][2 * N_NODES][FC1];// compacted gathered W2 cols [s][c'][k] (tf32)
__device__ float g_U1[N_NODES * LB];       // U[:,:,i1]  [n][t]  (tf32)
__device__ float g_U2[N_NODES * LB];       // U[:,:,i2]  [n][t]  (tf32)
__device__ float g_P [N_NODES * LB];       // U2 @ B^T   [m][f]  (tf32)

__device__ __forceinline__ float to_tf32(float x) {
    uint32_t u;
    asm("cvt.rna.tf32.f32 %0, %1;" : "=r"(u) : "f"(x));
    return __uint_as_float(u);
}
__device__ __forceinline__ void cp_async16(uint32_t dst, const void* src) {
    asm volatile("cp.async.ca.shared.global [%0], [%1], 16;" :: "r"(dst), "l"(src));
}

#define MMA_TF32(c, a, b)                                                          \
    asm volatile("mma.sync.aligned.m16n8k8.row.col.f32.tf32.tf32.f32 "             \
                 "{%0,%1,%2,%3},{%4,%5,%6,%7},{%8,%9},{%0,%1,%2,%3};"              \
                 : "+f"(c[0]), "+f"(c[1]), "+f"(c[2]), "+f"(c[3])                  \
                 : "r"(a[0]), "r"(a[1]), "r"(a[2]), "r"(a[3]), "r"(b[0]), "r"(b[1]))

// ---------------- kernel 1: spatial hidden, split-K, coalesced ------------
// grid (8 k-tiles of 32, 25 j-splits of 80), block 256
__global__ __launch_bounds__(256) void k_hid_s(const float* __restrict__ li,
                                               const float* __restrict__ Ws1) {
    __shared__ float smA[16 * 132];
    __shared__ float smW[16 * 36];
    const int k0 = blockIdx.x * 32;
    const int j0 = blockIdx.y * 80;
    const int tid = threadIdx.x;
    const int tx = tid & 7;
    const int ty = tid >> 3;

    float acc[4][4];
#pragma unroll
    for (int u = 0; u < 4; u++)
#pragma unroll
        for (int v = 0; v < 4; v++) acc[u][v] = 0.f;

    for (int jb = 0; jb < 80; jb += 16) {
        __syncthreads();
#pragma unroll
        for (int it = 0; it < 8; it++) {
            int e = tid + it * 256;
            int t = e >> 4, jj = e & 15;
            smA[jj * 132 + t] = li[t * N_NODES + j0 + jb + jj];
        }
#pragma unroll
        for (int it = 0; it < 2; it++) {
            int e = tid + it * 256;
            int jj = e >> 5, kk = e & 31;
            smW[jj * 36 + kk] = Ws1[(j0 + jb + jj) * FC1 + k0 + kk];
        }
        __syncthreads();
#pragma unroll
        for (int jj = 0; jj < 16; jj++) {
            float4 a = *(const float4*)&smA[jj * 132 + ty * 4];
            float4 w = *(const float4*)&smW[jj * 36 + tx * 4];
            float av[4] = {a.x, a.y, a.z, a.w};
            float wv[4] = {w.x, w.y, w.z, w.w};
#pragma unroll
            for (int u = 0; u < 4; u++)
#pragma unroll
                for (int v = 0; v < 4; v++) acc[u][v] += av[u] * wv[v];
        }
    }
    const int sp = blockIdx.y;
#pragma unroll
    for (int u = 0; u < 4; u++) {
        int t = ty * 4 + u;
        float4 v = make_float4(acc[u][0], acc[u][1], acc[u][2], acc[u][3]);
        *(float4*)&g_accP[sp][t * FC1 + k0 + tx * 4] = v;
    }
}

// ---------------- kernel 2: finalize hidden, store [t][k] tf32 ------------
// grid 128 (t), block 256 (k)
__global__ void k_hid_fin(const float* __restrict__ tf, const float* __restrict__ Wt1,
                          const float* __restrict__ bs1, const float* __restrict__ bt1) {
    const int t = blockIdx.x;
    const int k = threadIdx.x;
    __shared__ float stf[TFEAT];
    if (k < TFEAT) stf[k] = tf[t * TFEAT + k];

    float hs = bs1[k];
#pragma unroll
    for (int s = 0; s < 25; s++) hs += g_accP[s][t * FC1 + k];
    g_Hs[t * FC1 + k] = to_tf32(fmaxf(hs, 0.f));

    __syncthreads();
    float a = bt1[k];
#pragma unroll
    for (int j = 0; j < TFEAT; j++)
        a += stf[j] * Wt1[j * FC1 + k];
    g_Ht[t * FC1 + k] = to_tf32(fmaxf(a, 0.f));
}

// ---------------- kernel 3a: pure gather of W2 columns (tf32) -------------
// grid 1000, block 256 (8 warps). warp -> one (tensor, c') pair; lanes over k.
__global__ __launch_bounds__(256) void k_gather(
    const float* __restrict__ Ws2, const float* __restrict__ Wt2,
    const int* __restrict__ idxp, const int* __restrict__ tdp) {

    const int idx = idxp[0];
    const int td  = tdp[0];
    const int i1  = (td >= 0) ? (idx - td) : idx;
    const int i2  = (td >= 0) ? idx        : (idx + td);

    const int gw   = blockIdx.x * 8 + (threadIdx.x >> 5);   // 0..7999
    const int lane = threadIdx.x & 31;
    const int s    = (gw >= 2 * N_NODES) ? 1 : 0;
    const int cp   = s ? (gw - 2 * N_NODES) : gw;           // 0..3999
    const int n    = cp >> 1;
    const long c   = (long)n * NFEAT + ((cp & 1) ? i2 : i1);
    const float* __restrict__ W = s ? Wt2 : Ws2;

    float v[8];
#pragma unroll
    for (int it = 0; it < 8; it++) {
        int k = lane + it * 32;
        v[it] = __ldg(&W[(long)k * (N_NODES * NFEAT) + c]);
    }
#pragma unroll
    for (int it = 0; it < 8; it++)
        g_Wc[s][cp][lane + it * 32] = to_tf32(v[it]);
}

// ---------------- kernel 3b: embed via tf32 mma, double-buffered ----------
// grid 126 (32 c' each), block 256 (8 warps: 4 t-strips x 2 c-strips of 16)
__global__ __launch_bounds__(256) void k_embed(
    const float* __restrict__ bs2, const float* __restrict__ bt2,
    const int* __restrict__ idxp, const int* __restrict__ tdp) {

    __shared__ float smH[2][2][128 * 20];   // [buf][s][t*20+k] : 40.96 KB
    __shared__ float smW[2][2][32 * 20];    // [buf][s][cc*20+k]: 10.24 KB
    __shared__ float smBs[32], smBt[32];

    const int idx = idxp[0];
    const int td  = tdp[0];
    const int i1  = (td >= 0) ? (idx - td) : idx;
    const int i2  = (td >= 0) ? idx        : (idx + td);

    const int c0  = blockIdx.x * 32;
    const int tid = threadIdx.x;
    const int warp = tid >> 5, lane = tid & 31;
    const int wt = warp & 3;          // t-strip of 32
    const int wc = warp >> 2;         // c-strip of 16
    const int g = lane >> 2, tg = lane & 3;

    if (tid < 32) {
        int cp = c0 + tid;
        float b1 = 0.f, b2 = 0.f;
        if (cp < 2 * N_NODES) {
            int c = (cp >> 1) * NFEAT + ((cp & 1) ? i2 : i1);
            b1 = bs2[c]; b2 = bt2[c];
        }
        smBs[tid] = b1; smBt[tid] = b2;
    }

    // cp.async coords
    const int hS  = tid >> 9;                 // unused helper (kept simple below)
    (void)hS;
    const uint32_t baseH = (uint32_t)__cvta_generic_to_shared(&smH[0][0][0]);
    const uint32_t baseW = (uint32_t)__cvta_generic_to_shared(&smW[0][0][0]);
    // H entries: 1024 per stage (e = tid + it*256): s=e>>9, row=(e&511)>>2, k4=(e&3)*4
    // W entries: 256 per stage (e = tid):           s=e>>7, cc=(e&127)>>2,  k4=(e&3)*4
    const int wS  = tid >> 7;
    const int wCC = (tid & 127) >> 2;
    const int wK4 = (tid & 3) * 4;
    int wCP = c0 + wCC; if (wCP >= 2 * N_NODES) wCP = 2 * N_NODES - 1;
    const float* wSrcBase = (wS ? &g_Wc[1][0][0] : &g_Wc[0][0][0]) + (long)wCP * FC1 + wK4;

#define EMB_ISSUE(st, b)                                                            \
    {                                                                               \
        int kc = (st) * 16;                                                         \
        _Pragma("unroll")                                                           \
        for (int it = 0; it < 4; it++) {                                            \
            int e = tid + it * 256;                                                 \
            int s = e >> 9, row = (e & 511) >> 2, k4 = (e & 3) * 4;                 \
            const float* src = (s ? g_Ht : g_Hs) + row * FC1 + kc + k4;             \
            cp_async16(baseH + ((b) * 5120 + s * 2560 + row * 20 + k4) * 4, src);   \
        }                                                                           \
        cp_async16(baseW + ((b) * 1280 + wS * 640 + wCC * 20 + wK4) * 4,            \
                   wSrcBase + kc);                                                  \
        asm volatile("cp.async.commit_group;");                                     \
    }

    float accS[2][2][4], accT[2][2][4];
#pragma unroll
    for (int i = 0; i < 2; i++)
#pragma unroll
        for (int j = 0; j < 2; j++)
#pragma unroll
            for (int q = 0; q < 4; q++) { accS[i][j][q] = 0.f; accT[i][j][q] = 0.f; }

    EMB_ISSUE(0, 0);
    for (int st = 0; st < 16; st++) {
        if (st < 15) EMB_ISSUE(st + 1, (st + 1) & 1);
        if (st < 15) { asm volatile("cp.async.wait_group 1;"); }
        else         { asm volatile("cp.async.wait_group 0;"); }
        __syncthreads();
        const float* sHs = &smH[st & 1][0][0];
        const float* sHt = &smH[st & 1][1][0];
        const float* sWs = &smW[st & 1][0][0];
        const float* sWt = &smW[st & 1][1][0];
#pragma unroll
        for (int ks = 0; ks < 2; ks++) {
            int k0 = ks * 8;
            uint32_t aS[2][4], aT[2][4];
#pragma unroll
            for (int i = 0; i < 2; i++) {
                int base = (wt * 32 + i * 16) * 20 + k0;
                aS[i][0] = __float_as_uint(sHs[base + g * 20 + tg]);
                aS[i][1] = __float_as_uint(sHs[base + (g + 8) * 20 + tg]);
                aS[i][2] = __float_as_uint(sHs[base + g * 20 + tg + 4]);
                aS[i][3] = __float_as_uint(sHs[base + (g + 8) * 20 + tg + 4]);
                aT[i][0] = __float_as_uint(sHt[base + g * 20 + tg]);
                aT[i][1] = __float_as_uint(sHt[base + (g + 8) * 20 + tg]);
                aT[i][2] = __float_as_uint(sHt[base + g * 20 + tg + 4]);
                aT[i][3] = __float_as_uint(sHt[base + (g + 8) * 20 + tg + 4]);
            }
            uint32_t bS[2][2], bT[2][2];
#pragma unroll
            for (int j = 0; j < 2; j++) {
                int bb = (wc * 16 + j * 8 + g) * 20 + k0 + tg;
                bS[j][0] = __float_as_uint(sWs[bb]);
                bS[j][1] = __float_as_uint(sWs[bb + 4]);
                bT[j][0] = __float_as_uint(sWt[bb]);
                bT[j][1] = __float_as_uint(sWt[bb + 4]);
            }
#pragma unroll
            for (int i = 0; i < 2; i++)
#pragma unroll
                for (int j = 0; j < 2; j++) {
                    MMA_TF32(accS[i][j], aS[i], bS[j]);
                    MMA_TF32(accT[i][j], aT[i], bT[j]);
                }
        }
        __syncthreads();
    }

    // epilogue: relu(s+bs) + relu(t+bt), scatter to U1/U2 by parity of c'
#pragma unroll
    for (int i = 0; i < 2; i++)
#pragma unroll
        for (int j = 0; j < 2; j++)
#pragma unroll
            for (int q = 0; q < 4; q++) {
                int t   = wt * 32 + i * 16 + g + ((q & 2) ? 8 : 0);
                int col = wc * 16 + j * 8 + 2 * tg + (q & 1);
                int cp  = c0 + col;
                if (cp < 2 * N_NODES) {
                    float v = fmaxf(accS[i][j][q] + smBs[col], 0.f)
                            + fmaxf(accT[i][j][q] + smBt[col], 0.f);
                    int n = cp >> 1;
                    if (cp & 1) g_U2[n * 128 + t] = to_tf32(v);
                    else        g_U1[n * 128 + t] = to_tf32(v);
                }
            }
}

// ---------------- kernel 4: P = U2 @ B^T via tf32 mma ---------------------
// grid 16 (m-tiles 128), block 256 (8 warps: 4 m-strips x 2 f-strips of 64)
__global__ __launch_bounds__(256) void k_u2b(const float* __restrict__ B) {
    __shared__ float smA[128 * 36];   // [m][g-chunk 32]
    __shared__ float smB[128 * 36];   // [f][g-chunk 32]
    const int m0  = blockIdx.x * 128;
    const int tid = threadIdx.x;
    const int warp = tid >> 5, lane = tid & 31;
    const int wm = warp & 3;          // m-strip of 32
    const int wf = warp >> 2;         // f-strip of 64
    const int g = lane >> 2, tg = lane & 3;

    float acc[2][8][4];
#pragma unroll
    for (int i = 0; i < 2; i++)
#pragma unroll
        for (int j = 0; j < 8; j++)
#pragma unroll
            for (int q = 0; q < 4; q++) acc[i][j][q] = 0.f;

    for (int gc = 0; gc < 128; gc += 32) {
        __syncthreads();
#pragma unroll
        for (int it = 0; it < 4; it++) {
            int e = tid + it * 256;
            int row = e >> 3, k4 = (e & 7) * 4;
            int m = m0 + row; if (m >= N_NODES) m = N_NODES - 1;
            *(float4*)&smA[row * 36 + k4] = *(const float4*)&g_U2[m * 128 + gc + k4];
            float4 b = *(const float4*)&B[row * 128 + gc + k4];
            b.x = to_tf32(b.x); b.y = to_tf32(b.y); b.z = to_tf32(b.z); b.w = to_tf32(b.w);
            *(float4*)&smB[row * 36 + k4] = b;
        }
        __syncthreads();
#pragma unroll
        for (int ks = 0; ks < 4; ks++) {
            int k0 = ks * 8;
            uint32_t af[2][4];
#pragma unroll
            for (int i = 0; i < 2; i++) {
                int base = (wm * 32 + i * 16) * 36 + k0;
                af[i][0] = __float_as_uint(smA[base + g * 36 + tg]);
                af[i][1] = __float_as_uint(smA[base + (g + 8) * 36 + tg]);
                af[i][2] = __float_as_uint(smA[base + g * 36 + tg + 4]);
                af[i][3] = __float_as_uint(smA[base + (g + 8) * 36 + tg + 4]);
            }
            uint32_t bf[8][2];
#pragma unroll
            for (int j = 0; j < 8; j++) {
                int bb = (wf * 64 + j * 8 + g) * 36 + k0 + tg;
                bf[j][0] = __float_as_uint(smB[bb]);
                bf[j][1] = __float_as_uint(smB[bb + 4]);
            }
#pragma unroll
            for (int i = 0; i < 2; i++)
#pragma unroll
                for (int j = 0; j < 8; j++)
                    MMA_TF32(acc[i][j], af[i], bf[j]);
        }
    }

#pragma unroll
    for (int i = 0; i < 2; i++)
#pragma unroll
        for (int j = 0; j < 8; j++) {
            int m = m0 + wm * 32 + i * 16 + g;
            int f = wf * 64 + j * 8 + 2 * tg;
            if (m < N_NODES) {
                float2 v0 = make_float2(to_tf32(acc[i][j][0]), to_tf32(acc[i][j][1]));
                *(float2*)&g_P[m * 128 + f] = v0;
            }
            if (m + 8 < N_NODES) {
                float2 v1 = make_float2(to_tf32(acc[i][j][2]), to_tf32(acc[i][j][3]));
                *(float2*)&g_P[(m + 8) * 128 + f] = v1;
            }
        }
}

// ---------------- kernel 5: x = U1 @ P^T (tf32 tensor cores) --------------
__global__ __launch_bounds__(256) void k_gemm(float* __restrict__ out) {
    __shared__ float smA[128 * 36];
    __shared__ float smB[128 * 36];
    const int n0 = blockIdx.y * 128;
    const int m0 = blockIdx.x * 128;
    const int tid = threadIdx.x;
    const int warp = tid >> 5, lane = tid & 31;
    const int wn = warp & 3;
    const int wm = warp >> 2;
    const int g = lane >> 2, tg = lane & 3;
    const int lrow = tid >> 3, lkk = (tid & 7) * 4;

    float acc[2][8][4];
#pragma unroll
    for (int i = 0; i < 2; i++)
#pragma unroll
        for (int j = 0; j < 8; j++)
#pragma unroll
            for (int q = 0; q < 4; q++) acc[i][j][q] = 0.f;

    float4 ra[4], rb[4];
#pragma unroll
    for (int it = 0; it < 4; it++) {
        int row = lrow + it * 32;
        ra[it] = (n0 + row < N_NODES) ? *(const float4*)&g_U1[(n0 + row) * 128 + lkk]
                                      : make_float4(0, 0, 0, 0);
        rb[it] = (m0 + row < N_NODES) ? *(const float4*)&g_P [(m0 + row) * 128 + lkk]
                                      : make_float4(0, 0, 0, 0);
    }

    for (int kc = 0; kc < 4; kc++) {
        __syncthreads();
#pragma unroll
        for (int it = 0; it < 4; it++) {
            int row = lrow + it * 32;
            *(float4*)&smA[row * 36 + lkk] = ra[it];
            *(float4*)&smB[row * 36 + lkk] = rb[it];
        }
        __syncthreads();
        if (kc < 3) {
            int kn = (kc + 1) * 32;
#pragma unroll
            for (int it = 0; it < 4; it++) {
                int row = lrow + it * 32;
                ra[it] = (n0 + row < N_NODES) ? *(const float4*)&g_U1[(n0 + row) * 128 + kn + lkk]
                                              : make_float4(0, 0, 0, 0);
                rb[it] = (m0 + row < N_NODES) ? *(const float4*)&g_P [(m0 + row) * 128 + kn + lkk]
                                              : make_float4(0, 0, 0, 0);
            }
        }
#pragma unroll
        for (int ks = 0; ks < 4; ks++) {
            int k0 = ks * 8;
            uint32_t af[2][4];
#pragma unroll
            for (int i = 0; i < 2; i++) {
                int base = (wn * 32 + i * 16) * 36 + k0;
                af[i][0] = __float_as_uint(smA[base + g * 36 + tg]);
                af[i][1] = __float_as_uint(smA[base + (g + 8) * 36 + tg]);
                af[i][2] = __float_as_uint(smA[base + g * 36 + tg + 4]);
                af[i][3] = __float_as_uint(smA[base + (g + 8) * 36 + tg + 4]);
            }
            uint32_t bf[8][2];
#pragma unroll
            for (int j = 0; j < 8; j++) {
                int bb = (wm * 64 + j * 8 + g) * 36 + k0 + tg;
                bf[j][0] = __float_as_uint(smB[bb]);
                bf[j][1] = __float_as_uint(smB[bb + 4]);
            }
#pragma unroll
            for (int i = 0; i < 2; i++)
#pragma unroll
                for (int j = 0; j < 8; j++)
                    MMA_TF32(acc[i][j], af[i], bf[j]);
        }
    }

#pragma unroll
    for (int i = 0; i < 2; i++) {
#pragma unroll
        for (int j = 0; j < 8; j++) {
            int n = n0 + wn * 32 + i * 16 + g;
            int m = m0 + wm * 64 + j * 8 + 2 * tg;
            if (m < N_NODES) {
                float2 v0, v1;
                v0.x = (acc[i][j][0] >= DELTA_MIN) ? acc[i][j][0] : 0.f;
                v0.y = (acc[i][j][1] >= DELTA_MIN) ? acc[i][j][1] : 0.f;
                v1.x = (acc[i][j][2] >= DELTA_MIN) ? acc[i][j][2] : 0.f;
                v1.y = (acc[i][j][3] >= DELTA_MIN) ? acc[i][j][3] : 0.f;
                if (n < N_NODES)     *(float2*)&out[(long)n * N_NODES + m] = v0;
                if (n + 8 < N_NODES) *(float2*)&out[(long)(n + 8) * N_NODES + m] = v1;
            }
        }
    }
}

// ---------------- kernel 6: in-place row softmax (float4) -----------------
__global__ void k_softmax(float* __restrict__ out) {
    const int row = blockIdx.x;
    float* p = out + (long)row * N_NODES;
    const int tid = threadIdx.x;
    const bool act = tid < 250;
    __shared__ float redM[8];
    __shared__ float redS[8];

    float4 v0, v1;
    float mx = -1e30f;
    if (act) {
        v0 = *(const float4*)&p[tid * 8];
        v1 = *(const float4*)&p[tid * 8 + 4];
        mx = fmaxf(fmaxf(fmaxf(v0.x, v0.y), fmaxf(v0.z, v0.w)),
                   fmaxf(fmaxf(v1.x, v1.y), fmaxf(v1.z, v1.w)));
    }
#pragma unroll
    for (int o = 16; o; o >>= 1) mx = fmaxf(mx, __shfl_xor_sync(0xFFFFFFFFu, mx, o));
    if ((tid & 31) == 0) redM[tid >> 5] = mx;
    __syncthreads();
    float gmax = redM[0];
#pragma unroll
    for (int w = 1; w < 8; w++) gmax = fmaxf(gmax, redM[w]);

    float s = 0.f;
    if (act) {
        v0.x = __expf(v0.x - gmax); v0.y = __expf(v0.y - gmax);
        v0.z = __expf(v0.z - gmax); v0.w = __expf(v0.w - gmax);
        v1.x = __expf(v1.x - gmax); v1.y = __expf(v1.y - gmax);
        v1.z = __expf(v1.z - gmax); v1.w = __expf(v1.w - gmax);
        s = v0.x + v0.y + v0.z + v0.w + v1.x + v1.y + v1.z + v1.w;
    }
#pragma unroll
    for (int o = 16; o; o >>= 1) s += __shfl_xor_sync(0xFFFFFFFFu, s, o);
    if ((tid & 31) == 0) redS[tid >> 5] = s;
    __syncthreads();
    float tot = 0.f;
#pragma unroll
    for (int w = 0; w < 8; w++) tot += redS[w];
    float inv = 1.f / tot;
    if (act) {
        v0.x *= inv; v0.y *= inv; v0.z *= inv; v0.w *= inv;
        v1.x *= inv; v1.y *= inv; v1.z *= inv; v1.w *= inv;
        *(float4*)&p[tid * 8]     = v0;
        *(float4*)&p[tid * 8 + 4] = v1;
    }
}

// ---------------- launch ---------------------------------------------------
extern "C" void kernel_launch(void* const* d_in, const int* in_sizes, int n_in,
                              void* d_out, int out_size) {
    const float* tf   = (const float*)d_in[0];
    const float* li   = (const float*)d_in[1];
    const float* Ws1  = (const float*)d_in[2];
    const float* bs1  = (const float*)d_in[3];
    const float* Ws2  = (const float*)d_in[4];
    const float* bs2  = (const float*)d_in[5];
    const float* Wt1  = (const float*)d_in[6];
    const float* bt1  = (const float*)d_in[7];
    const float* Wt2  = (const float*)d_in[8];
    const float* bt2  = (const float*)d_in[9];
    const float* B    = (const float*)d_in[10];
    const int*   idxp = (const int*)d_in[11];
    const int*   tdp  = (const int*)d_in[12];
    float* out = (float*)d_out;

    k_gather <<<1000, 256>>>(Ws2, Wt2, idxp, tdp);
    k_hid_s  <<<dim3(8, 25), 256>>>(li, Ws1);
    k_hid_fin<<<128, 256>>>(tf, Wt1, bs1, bt1);
    k_embed  <<<126, 256>>>(bs2, bt2, idxp, tdp);
    k_u2b    <<<16, 256>>>(B);
    k_gemm   <<<dim3(16, 16), 256>>>(out);
    k_softmax<<<2000, 256>>>(out);
}

// round 8
// speedup vs baseline: 1.2797x; 1.0245x over previous
#include <cuda_runtime.h>
#include <math.h>
#include <stdint.h>

#define N_NODES 2000
#define NFEAT   128
#define LB      128
#define TFEAT   36
#define FC1     256
#define DELTA_MIN 0.05f

// ---------------- scratch (device globals; no allocation) ----------------
__device__ float g_accP[25][FC1 * LB];     // split-K partials, [split][t*256 + k]
__device__ float g_Hs[LB * FC1];           // relu spatial hidden, [t][k] (tf32)
__device__ float g_Ht[LB * FC1];           // relu temporal hidden, [t][k] (tf32)
__device__ float g_U1[N_NODES * LB];       // U[:,:,i1]  [n][t]  (tf32)
__device__ float g_U2[N_NODES * LB];       // U[:,:,i2]  [n][t]  (tf32)
__device__ float g_P [N_NODES * LB];       // U2 @ B^T   [m][f]  (tf32)

__device__ __forceinline__ float to_tf32(float x) {
    uint32_t u;
    asm("cvt.rna.tf32.f32 %0, %1;" : "=r"(u) : "f"(x));
    return __uint_as_float(u);
}
__device__ __forceinline__ void cp_async16(uint32_t dst, const void* src) {
    asm volatile("cp.async.ca.shared.global [%0], [%1], 16;" :: "r"(dst), "l"(src));
}
__device__ __forceinline__ void cp_async4(uint32_t dst, const void* src) {
    asm volatile("cp.async.ca.shared.global [%0], [%1], 4;" :: "r"(dst), "l"(src));
}

#define MMA_TF32(c, a, b)                                                          \
    asm volatile("mma.sync.aligned.m16n8k8.row.col.f32.tf32.tf32.f32 "             \
                 "{%0,%1,%2,%3},{%4,%5,%6,%7},{%8,%9},{%0,%1,%2,%3};"              \
                 : "+f"(c[0]), "+f"(c[1]), "+f"(c[2]), "+f"(c[3])                  \
                 : "r"(a[0]), "r"(a[1]), "r"(a[2]), "r"(a[3]), "r"(b[0]), "r"(b[1]))

// ---------------- kernel 1: spatial hidden, split-K, coalesced ------------
// grid (8 k-tiles of 32, 25 j-splits of 80), block 256
__global__ __launch_bounds__(256) void k_hid_s(const float* __restrict__ li,
                                               const float* __restrict__ Ws1) {
    __shared__ float smA[16 * 132];
    __shared__ float smW[16 * 36];
    const int k0 = blockIdx.x * 32;
    const int j0 = blockIdx.y * 80;
    const int tid = threadIdx.x;
    const int tx = tid & 7;
    const int ty = tid >> 3;

    float acc[4][4];
#pragma unroll
    for (int u = 0; u < 4; u++)
#pragma unroll
        for (int v = 0; v < 4; v++) acc[u][v] = 0.f;

    for (int jb = 0; jb < 80; jb += 16) {
        __syncthreads();
#pragma unroll
        for (int it = 0; it < 8; it++) {
            int e = tid + it * 256;
            int t = e >> 4, jj = e & 15;
            smA[jj * 132 + t] = li[t * N_NODES + j0 + jb + jj];
        }
#pragma unroll
        for (int it = 0; it < 2; it++) {
            int e = tid + it * 256;
            int jj = e >> 5, kk = e & 31;
            smW[jj * 36 + kk] = Ws1[(j0 + jb + jj) * FC1 + k0 + kk];
        }
        __syncthreads();
#pragma unroll
        for (int jj = 0; jj < 16; jj++) {
            float4 a = *(const float4*)&smA[jj * 132 + ty * 4];
            float4 w = *(const float4*)&smW[jj * 36 + tx * 4];
            float av[4] = {a.x, a.y, a.z, a.w};
            float wv[4] = {w.x, w.y, w.z, w.w};
#pragma unroll
            for (int u = 0; u < 4; u++)
#pragma unroll
                for (int v = 0; v < 4; v++) acc[u][v] += av[u] * wv[v];
        }
    }
    const int sp = blockIdx.y;
#pragma unroll
    for (int u = 0; u < 4; u++) {
        int t = ty * 4 + u;
        float4 v = make_float4(acc[u][0], acc[u][1], acc[u][2], acc[u][3]);
        *(float4*)&g_accP[sp][t * FC1 + k0 + tx * 4] = v;
    }
}

// ---------------- kernel 2: finalize hidden, store [t][k] tf32 ------------
// grid 128 (t), block 256 (k)
__global__ void k_hid_fin(const float* __restrict__ tf, const float* __restrict__ Wt1,
                          const float* __restrict__ bs1, const float* __restrict__ bt1) {
    const int t = blockIdx.x;
    const int k = threadIdx.x;
    __shared__ float stf[TFEAT];
    if (k < TFEAT) stf[k] = tf[t * TFEAT + k];

    float hs = bs1[k];
#pragma unroll
    for (int s = 0; s < 25; s++) hs += g_accP[s][t * FC1 + k];
    g_Hs[t * FC1 + k] = to_tf32(fmaxf(hs, 0.f));

    __syncthreads();
    float a = bt1[k];
#pragma unroll
    for (int j = 0; j < TFEAT; j++)
        a += stf[j] * Wt1[j * FC1 + k];
    g_Ht[t * FC1 + k] = to_tf32(fmaxf(a, 0.f));
}

// ---------------- kernel 3: embed via tf32 mma, fused W gather ------------
// grid 126 (32 c' each), block 256 (8 warps: 4 t-strips x 2 c-strips of 16)
// W tiles gathered straight from Ws2/Wt2 with 4B scattered cp.async.
__global__ __launch_bounds__(256) void k_embed(
    const float* __restrict__ Ws2, const float* __restrict__ Wt2,
    const float* __restrict__ bs2, const float* __restrict__ bt2,
    const int* __restrict__ idxp, const int* __restrict__ tdp) {

    __shared__ float smH[2][2][128 * 20];   // [buf][s][t*20+k] : 40.96 KB
    __shared__ float smW[2][2][32 * 20];    // [buf][s][cc*20+k]: 10.24 KB
    __shared__ float smBs[32], smBt[32];

    const int idx = idxp[0];
    const int td  = tdp[0];
    const int i1  = (td >= 0) ? (idx - td) : idx;
    const int i2  = (td >= 0) ? idx        : (idx + td);

    const int c0  = blockIdx.x * 32;
    const int tid = threadIdx.x;
    const int warp = tid >> 5, lane = tid & 31;
    const int wt = warp & 3;          // t-strip of 32
    const int wc = warp >> 2;         // c-strip of 16
    const int g = lane >> 2, tg = lane & 3;

    if (tid < 32) {
        int cp = c0 + tid;
        float b1 = 0.f, b2 = 0.f;
        if (cp < 2 * N_NODES) {
            int c = (cp >> 1) * NFEAT + ((cp & 1) ? i2 : i1);
            b1 = bs2[c]; b2 = bt2[c];
        }
        smBs[tid] = b1; smBt[tid] = b2;
    }

    const uint32_t baseH = (uint32_t)__cvta_generic_to_shared(&smH[0][0][0]);
    const uint32_t baseW = (uint32_t)__cvta_generic_to_shared(&smW[0][0][0]);

    // W gather coords: 1024 elements/stage (32 cc x 16 kk x 2 s), 4 per thread.
    // e = tid + it*256 : s = e>>9, cc = (e&511)>>4, kk = e&15
    const float* wSrc[4];
    uint32_t     wDst[4];   // relative (floats), add buf offset later
#pragma unroll
    for (int it = 0; it < 4; it++) {
        int e  = tid + it * 256;
        int s  = e >> 9;
        int cc = (e & 511) >> 4;
        int kk = e & 15;
        int cp = c0 + cc; if (cp >= 2 * N_NODES) cp = 2 * N_NODES - 1;
        long c = (long)(cp >> 1) * NFEAT + ((cp & 1) ? i2 : i1);
        wSrc[it] = (s ? Wt2 : Ws2) + (long)kk * (N_NODES * NFEAT) + c;
        wDst[it] = (uint32_t)(s * 640 + cc * 20 + kk);
    }

#define EMB_ISSUE(st, b)                                                            \
    {                                                                               \
        int kc = (st) * 16;                                                         \
        _Pragma("unroll")                                                           \
        for (int it = 0; it < 4; it++) {                                            \
            int e = tid + it * 256;                                                 \
            int s = e >> 9, row = (e & 511) >> 2, k4 = (e & 3) * 4;                 \
            const float* src = (s ? g_Ht : g_Hs) + row * FC1 + kc + k4;             \
            cp_async16(baseH + ((b) * 5120 + s * 2560 + row * 20 + k4) * 4, src);   \
        }                                                                           \
        _Pragma("unroll")                                                           \
        for (int it = 0; it < 4; it++)                                              \
            cp_async4(baseW + ((b) * 1280 + wDst[it]) * 4,                          \
                      wSrc[it] + (long)kc * (N_NODES * NFEAT));                     \
        asm volatile("cp.async.commit_group;");                                     \
    }

    float accS[2][2][4], accT[2][2][4];
#pragma unroll
    for (int i = 0; i < 2; i++)
#pragma unroll
        for (int j = 0; j < 2; j++)
#pragma unroll
            for (int q = 0; q < 4; q++) { accS[i][j][q] = 0.f; accT[i][j][q] = 0.f; }

    EMB_ISSUE(0, 0);
    for (int st = 0; st < 16; st++) {
        if (st < 15) EMB_ISSUE(st + 1, (st + 1) & 1);
        if (st < 15) { asm volatile("cp.async.wait_group 1;"); }
        else         { asm volatile("cp.async.wait_group 0;"); }
        __syncthreads();
        const float* sHs = &smH[st & 1][0][0];
        const float* sHt = &smH[st & 1][1][0];
        const float* sWs = &smW[st & 1][0][0];
        const float* sWt = &smW[st & 1][1][0];
#pragma unroll
        for (int ks = 0; ks < 2; ks++) {
            int k0 = ks * 8;
            uint32_t aS[2][4], aT[2][4];
#pragma unroll
            for (int i = 0; i < 2; i++) {
                int base = (wt * 32 + i * 16) * 20 + k0;
                aS[i][0] = __float_as_uint(sHs[base + g * 20 + tg]);
                aS[i][1] = __float_as_uint(sHs[base + (g + 8) * 20 + tg]);
                aS[i][2] = __float_as_uint(sHs[base + g * 20 + tg + 4]);
                aS[i][3] = __float_as_uint(sHs[base + (g + 8) * 20 + tg + 4]);
                aT[i][0] = __float_as_uint(sHt[base + g * 20 + tg]);
                aT[i][1] = __float_as_uint(sHt[base + (g + 8) * 20 + tg]);
                aT[i][2] = __float_as_uint(sHt[base + g * 20 + tg + 4]);
                aT[i][3] = __float_as_uint(sHt[base + (g + 8) * 20 + tg + 4]);
            }
            uint32_t bS[2][2], bT[2][2];
#pragma unroll
            for (int j = 0; j < 2; j++) {
                int bb = (wc * 16 + j * 8 + g) * 20 + k0 + tg;
                bS[j][0] = __float_as_uint(sWs[bb]);
                bS[j][1] = __float_as_uint(sWs[bb + 4]);
                bT[j][0] = __float_as_uint(sWt[bb]);
                bT[j][1] = __float_as_uint(sWt[bb + 4]);
            }
#pragma unroll
            for (int i = 0; i < 2; i++)
#pragma unroll
                for (int j = 0; j < 2; j++) {
                    MMA_TF32(accS[i][j], aS[i], bS[j]);
                    MMA_TF32(accT[i][j], aT[i], bT[j]);
                }
        }
        __syncthreads();
    }

    // epilogue: relu(s+bs) + relu(t+bt), scatter to U1/U2 by parity of c'
#pragma unroll
    for (int i = 0; i < 2; i++)
#pragma unroll
        for (int j = 0; j < 2; j++)
#pragma unroll
            for (int q = 0; q < 4; q++) {
                int t   = wt * 32 + i * 16 + g + ((q & 2) ? 8 : 0);
                int col = wc * 16 + j * 8 + 2 * tg + (q & 1);
                int cp  = c0 + col;
                if (cp < 2 * N_NODES) {
                    float v = fmaxf(accS[i][j][q] + smBs[col], 0.f)
                            + fmaxf(accT[i][j][q] + smBt[col], 0.f);
                    int n = cp >> 1;
                    if (cp & 1) g_U2[n * 128 + t] = to_tf32(v);
                    else        g_U1[n * 128 + t] = to_tf32(v);
                }
            }
}

// ---------------- kernel 4: P = U2 @ B^T via tf32 mma ---------------------
// grid 16 (m-tiles 128), block 256 (8 warps: 4 m-strips x 2 f-strips of 64)
__global__ __launch_bounds__(256) void k_u2b(const float* __restrict__ B) {
    __shared__ float smA[128 * 36];   // [m][g-chunk 32]
    __shared__ float smB[128 * 36];   // [f][g-chunk 32]
    const int m0  = blockIdx.x * 128;
    const int tid = threadIdx.x;
    const int warp = tid >> 5, lane = tid & 31;
    const int wm = warp & 3;          // m-strip of 32
    const int wf = warp >> 2;         // f-strip of 64
    const int g = lane >> 2, tg = lane & 3;

    float acc[2][8][4];
#pragma unroll
    for (int i = 0; i < 2; i++)
#pragma unroll
        for (int j = 0; j < 8; j++)
#pragma unroll
            for (int q = 0; q < 4; q++) acc[i][j][q] = 0.f;

    for (int gc = 0; gc < 128; gc += 32) {
        __syncthreads();
#pragma unroll
        for (int it = 0; it < 4; it++) {
            int e = tid + it * 256;
            int row = e >> 3, k4 = (e & 7) * 4;
            int m = m0 + row; if (m >= N_NODES) m = N_NODES - 1;
            *(float4*)&smA[row * 36 + k4] = *(const float4*)&g_U2[m * 128 + gc + k4];
            float4 b = *(const float4*)&B[row * 128 + gc + k4];
            b.x = to_tf32(b.x); b.y = to_tf32(b.y); b.z = to_tf32(b.z); b.w = to_tf32(b.w);
            *(float4*)&smB[row * 36 + k4] = b;
        }
        __syncthreads();
#pragma unroll
        for (int ks = 0; ks < 4; ks++) {
            int k0 = ks * 8;
            uint32_t af[2][4];
#pragma unroll
            for (int i = 0; i < 2; i++) {
                int base = (wm * 32 + i * 16) * 36 + k0;
                af[i][0] = __float_as_uint(smA[base + g * 36 + tg]);
                af[i][1] = __float_as_uint(smA[base + (g + 8) * 36 + tg]);
                af[i][2] = __float_as_uint(smA[base + g * 36 + tg + 4]);
                af[i][3] = __float_as_uint(smA[base + (g + 8) * 36 + tg + 4]);
            }
            uint32_t bf[8][2];
#pragma unroll
            for (int j = 0; j < 8; j++) {
                int bb = (wf * 64 + j * 8 + g) * 36 + k0 + tg;
                bf[j][0] = __float_as_uint(smB[bb]);
                bf[j][1] = __float_as_uint(smB[bb + 4]);
            }
#pragma unroll
            for (int i = 0; i < 2; i++)
#pragma unroll
                for (int j = 0; j < 8; j++)
                    MMA_TF32(acc[i][j], af[i], bf[j]);
        }
    }

#pragma unroll
    for (int i = 0; i < 2; i++)
#pragma unroll
        for (int j = 0; j < 8; j++) {
            int m = m0 + wm * 32 + i * 16 + g;
            int f = wf * 64 + j * 8 + 2 * tg;
            if (m < N_NODES) {
                float2 v0 = make_float2(to_tf32(acc[i][j][0]), to_tf32(acc[i][j][1]));
                *(float2*)&g_P[m * 128 + f] = v0;
            }
            if (m + 8 < N_NODES) {
                float2 v1 = make_float2(to_tf32(acc[i][j][2]), to_tf32(acc[i][j][3]));
                *(float2*)&g_P[(m + 8) * 128 + f] = v1;
            }
        }
}

// ---------------- kernel 5: x = U1 @ P^T (tf32 tensor cores) --------------
__global__ __launch_bounds__(256) void k_gemm(float* __restrict__ out) {
    __shared__ float smA[128 * 36];
    __shared__ float smB[128 * 36];
    const int n0 = blockIdx.y * 128;
    const int m0 = blockIdx.x * 128;
    const int tid = threadIdx.x;
    const int warp = tid >> 5, lane = tid & 31;
    const int wn = warp & 3;
    const int wm = warp >> 2;
    const int g = lane >> 2, tg = lane & 3;
    const int lrow = tid >> 3, lkk = (tid & 7) * 4;

    float acc[2][8][4];
#pragma unroll
    for (int i = 0; i < 2; i++)
#pragma unroll
        for (int j = 0; j < 8; j++)
#pragma unroll
            for (int q = 0; q < 4; q++) acc[i][j][q] = 0.f;

    float4 ra[4], rb[4];
#pragma unroll
    for (int it = 0; it < 4; it++) {
        int row = lrow + it * 32;
        ra[it] = (n0 + row < N_NODES) ? *(const float4*)&g_U1[(n0 + row) * 128 + lkk]
                                      : make_float4(0, 0, 0, 0);
        rb[it] = (m0 + row < N_NODES) ? *(const float4*)&g_P [(m0 + row) * 128 + lkk]
                                      : make_float4(0, 0, 0, 0);
    }

    for (int kc = 0; kc < 4; kc++) {
        __syncthreads();
#pragma unroll
        for (int it = 0; it < 4; it++) {
            int row = lrow + it * 32;
            *(float4*)&smA[row * 36 + lkk] = ra[it];
            *(float4*)&smB[row * 36 + lkk] = rb[it];
        }
        __syncthreads();
        if (kc < 3) {
            int kn = (kc + 1) * 32;
#pragma unroll
            for (int it = 0; it < 4; it++) {
                int row = lrow + it * 32;
                ra[it] = (n0 + row < N_NODES) ? *(const float4*)&g_U1[(n0 + row) * 128 + kn + lkk]
                                              : make_float4(0, 0, 0, 0);
                rb[it] = (m0 + row < N_NODES) ? *(const float4*)&g_P [(m0 + row) * 128 + kn + lkk]
                                              : make_float4(0, 0, 0, 0);
            }
        }
#pragma unroll
        for (int ks = 0; ks < 4; ks++) {
            int k0 = ks * 8;
            uint32_t af[2][4];
#pragma unroll
            for (int i = 0; i < 2; i++) {
                int base = (wn * 32 + i * 16) * 36 + k0;
                af[i][0] = __float_as_uint(smA[base + g * 36 + tg]);
                af[i][1] = __float_as_uint(smA[base + (g + 8) * 36 + tg]);
                af[i][2] = __float_as_uint(smA[base + g * 36 + tg + 4]);
                af[i][3] = __float_as_uint(smA[base + (g + 8) * 36 + tg + 4]);
            }
            uint32_t bf[8][2];
#pragma unroll
            for (int j = 0; j < 8; j++) {
                int bb = (wm * 64 + j * 8 + g) * 36 + k0 + tg;
                bf[j][0] = __float_as_uint(smB[bb]);
                bf[j][1] = __float_as_uint(smB[bb + 4]);
            }
#pragma unroll
            for (int i = 0; i < 2; i++)
#pragma unroll
                for (int j = 0; j < 8; j++)
                    MMA_TF32(acc[i][j], af[i], bf[j]);
        }
    }

#pragma unroll
    for (int i = 0; i < 2; i++) {
#pragma unroll
        for (int j = 0; j < 8; j++) {
            int n = n0 + wn * 32 + i * 16 + g;
            int m = m0 + wm * 64 + j * 8 + 2 * tg;
            if (m < N_NODES) {
                float2 v0, v1;
                v0.x = (acc[i][j][0] >= DELTA_MIN) ? acc[i][j][0] : 0.f;
                v0.y = (acc[i][j][1] >= DELTA_MIN) ? acc[i][j][1] : 0.f;
                v1.x = (acc[i][j][2] >= DELTA_MIN) ? acc[i][j][2] : 0.f;
                v1.y = (acc[i][j][3] >= DELTA_MIN) ? acc[i][j][3] : 0.f;
                if (n < N_NODES)     *(float2*)&out[(long)n * N_NODES + m] = v0;
                if (n + 8 < N_NODES) *(float2*)&out[(long)(n + 8) * N_NODES + m] = v1;
            }
        }
    }
}

// ---------------- kernel 6: in-place row softmax (float4) -----------------
__global__ void k_softmax(float* __restrict__ out) {
    const int row = blockIdx.x;
    float* p = out + (long)row * N_NODES;
    const int tid = threadIdx.x;
    const bool act = tid < 250;
    __shared__ float redM[8];
    __shared__ float redS[8];

    float4 v0, v1;
    float mx = -1e30f;
    if (act) {
        v0 = *(const float4*)&p[tid * 8];
        v1 = *(const float4*)&p[tid * 8 + 4];
        mx = fmaxf(fmaxf(fmaxf(v0.x, v0.y), fmaxf(v0.z, v0.w)),
                   fmaxf(fmaxf(v1.x, v1.y), fmaxf(v1.z, v1.w)));
    }
#pragma unroll
    for (int o = 16; o; o >>= 1) mx = fmaxf(mx, __shfl_xor_sync(0xFFFFFFFFu, mx, o));
    if ((tid & 31) == 0) redM[tid >> 5] = mx;
    __syncthreads();
    float gmax = redM[0];
#pragma unroll
    for (int w = 1; w < 8; w++) gmax = fmaxf(gmax, redM[w]);

    float s = 0.f;
    if (act) {
        v0.x = __expf(v0.x - gmax); v0.y = __expf(v0.y - gmax);
        v0.z = __expf(v0.z - gmax); v0.w = __expf(v0.w - gmax);
        v1.x = __expf(v1.x - gmax); v1.y = __expf(v1.y - gmax);
        v1.z = __expf(v1.z - gmax); v1.w = __expf(v1.w - gmax);
        s = v0.x + v0.y + v0.z + v0.w + v1.x + v1.y + v1.z + v1.w;
    }
#pragma unroll
    for (int o = 16; o; o >>= 1) s += __shfl_xor_sync(0xFFFFFFFFu, s, o);
    if ((tid & 31) == 0) redS[tid >> 5] = s;
    __syncthreads();
    float tot = 0.f;
#pragma unroll
    for (int w = 0; w < 8; w++) tot += redS[w];
    float inv = 1.f / tot;
    if (act) {
        v0.x *= inv; v0.y *= inv; v0.z *= inv; v0.w *= inv;
        v1.x *= inv; v1.y *= inv; v1.z *= inv; v1.w *= inv;
        *(float4*)&p[tid * 8]     = v0;
        *(float4*)&p[tid * 8 + 4] = v1;
    }
}

// ---------------- launch ---------------------------------------------------
extern "C" void kernel_launch(void* const* d_in, const int* in_sizes, int n_in,
                              void* d_out, int out_size) {
    const float* tf   = (const float*)d_in[0];
    const float* li   = (const float*)d_in[1];
    const float* Ws1  = (const float*)d_in[2];
    const float* bs1  = (const float*)d_in[3];
    const float* Ws2  = (const float*)d_in[4];
    const float* bs2  = (const float*)d_in[5];
    const float* Wt1  = (const float*)d_in[6];
    const float* bt1  = (const float*)d_in[7];
    const float* Wt2  = (const float*)d_in[8];
    const float* bt2  = (const float*)d_in[9];
    const float* B    = (const float*)d_in[10];
    const int*   idxp = (const int*)d_in[11];
    const int*   tdp  = (const int*)d_in[12];
    float* out = (float*)d_out;

    k_hid_s  <<<dim3(8, 25), 256>>>(li, Ws1);
    k_hid_fin<<<128, 256>>>(tf, Wt1, bs1, bt1);
    k_embed  <<<126, 256>>>(Ws2, Wt2, bs2, bt2, idxp, tdp);
    k_u2b    <<<16, 256>>>(B);
    k_gemm   <<<dim3(16, 16), 256>>>(out);
    k_softmax<<<2000, 256>>>(out);
}

// round 9
// speedup vs baseline: 1.5993x; 1.2497x over previous
#include <cuda_runtime.h>
#include <math.h>
#include <stdint.h>

#define N_NODES 2000
#define NFEAT   128
#define LB      128
#define TFEAT   36
#define FC1     256
#define DELTA_MIN 0.05f

// ---------------- scratch (device globals; no allocation) ----------------
__device__ float g_accP[25][FC1 * LB];     // split-K partials, [split][t*256 + k]
__device__ float g_Hs[LB * FC1];           // relu spatial hidden, [t][k] (tf32)
__device__ float g_Ht[LB * FC1];           // relu temporal hidden, [t][k] (tf32)
__device__ float g_U1[N_NODES * LB];       // U[:,:,i1]  [n][t]  (tf32)
__device__ float g_U2[N_NODES * LB];       // U[:,:,i2]  [n][t]  (tf32)
__device__ float g_P [N_NODES * LB];       // U2 @ B^T   [m][f]  (tf32)

__device__ __forceinline__ float to_tf32(float x) {
    uint32_t u;
    asm("cvt.rna.tf32.f32 %0, %1;" : "=r"(u) : "f"(x));
    return __uint_as_float(u);
}
__device__ __forceinline__ void cp_async16(uint32_t dst, const void* src) {
    asm volatile("cp.async.ca.shared.global [%0], [%1], 16;" :: "r"(dst), "l"(src));
}
__device__ __forceinline__ void cp_async16z(uint32_t dst, const void* src, int ssize) {
    asm volatile("cp.async.ca.shared.global [%0], [%1], 16, %2;"
                 :: "r"(dst), "l"(src), "r"(ssize));
}
__device__ __forceinline__ void cp_async4(uint32_t dst, const void* src) {
    asm volatile("cp.async.ca.shared.global [%0], [%1], 4;" :: "r"(dst), "l"(src));
}

#define MMA_TF32(c, a, b)                                                          \
    asm volatile("mma.sync.aligned.m16n8k8.row.col.f32.tf32.tf32.f32 "             \
                 "{%0,%1,%2,%3},{%4,%5,%6,%7},{%8,%9},{%0,%1,%2,%3};"              \
                 : "+f"(c[0]), "+f"(c[1]), "+f"(c[2]), "+f"(c[3])                  \
                 : "r"(a[0]), "r"(a[1]), "r"(a[2]), "r"(a[3]), "r"(b[0]), "r"(b[1]))

// ---------------- kernel 1: spatial hidden, split-K, coalesced ------------
// grid (8 k-tiles of 32, 25 j-splits of 80), block 256
__global__ __launch_bounds__(256) void k_hid_s(const float* __restrict__ li,
                                               const float* __restrict__ Ws1) {
    __shared__ float smA[16 * 132];
    __shared__ float smW[16 * 36];
    const int k0 = blockIdx.x * 32;
    const int j0 = blockIdx.y * 80;
    const int tid = threadIdx.x;
    const int tx = tid & 7;
    const int ty = tid >> 3;

    float acc[4][4];
#pragma unroll
    for (int u = 0; u < 4; u++)
#pragma unroll
        for (int v = 0; v < 4; v++) acc[u][v] = 0.f;

    for (int jb = 0; jb < 80; jb += 16) {
        __syncthreads();
#pragma unroll
        for (int it = 0; it < 8; it++) {
            int e = tid + it * 256;
            int t = e >> 4, jj = e & 15;
            smA[jj * 132 + t] = li[t * N_NODES + j0 + jb + jj];
        }
#pragma unroll
        for (int it = 0; it < 2; it++) {
            int e = tid + it * 256;
            int jj = e >> 5, kk = e & 31;
            smW[jj * 36 + kk] = Ws1[(j0 + jb + jj) * FC1 + k0 + kk];
        }
        __syncthreads();
#pragma unroll
        for (int jj = 0; jj < 16; jj++) {
            float4 a = *(const float4*)&smA[jj * 132 + ty * 4];
            float4 w = *(const float4*)&smW[jj * 36 + tx * 4];
            float av[4] = {a.x, a.y, a.z, a.w};
            float wv[4] = {w.x, w.y, w.z, w.w};
#pragma unroll
            for (int u = 0; u < 4; u++)
#pragma unroll
                for (int v = 0; v < 4; v++) acc[u][v] += av[u] * wv[v];
        }
    }
    const int sp = blockIdx.y;
#pragma unroll
    for (int u = 0; u < 4; u++) {
        int t = ty * 4 + u;
        float4 v = make_float4(acc[u][0], acc[u][1], acc[u][2], acc[u][3]);
        *(float4*)&g_accP[sp][t * FC1 + k0 + tx * 4] = v;
    }
}

// ---------------- kernel 2: finalize hidden, store [t][k] tf32 ------------
// grid 128 (t), block 256 (k)
__global__ void k_hid_fin(const float* __restrict__ tf, const float* __restrict__ Wt1,
                          const float* __restrict__ bs1, const float* __restrict__ bt1) {
    const int t = blockIdx.x;
    const int k = threadIdx.x;
    __shared__ float stf[TFEAT];
    if (k < TFEAT) stf[k] = tf[t * TFEAT + k];

    float hs = bs1[k];
#pragma unroll
    for (int s = 0; s < 25; s++) hs += g_accP[s][t * FC1 + k];
    g_Hs[t * FC1 + k] = to_tf32(fmaxf(hs, 0.f));

    __syncthreads();
    float a = bt1[k];
#pragma unroll
    for (int j = 0; j < TFEAT; j++)
        a += stf[j] * Wt1[j * FC1 + k];
    g_Ht[t * FC1 + k] = to_tf32(fmaxf(a, 0.f));
}

// ---------------- kernel 3: embed via tf32 mma, fused W gather ------------
// grid 126 (32 c' each), block 256 (8 warps: 4 t-strips x 2 c-strips of 16)
__global__ __launch_bounds__(256) void k_embed(
    const float* __restrict__ Ws2, const float* __restrict__ Wt2,
    const float* __restrict__ bs2, const float* __restrict__ bt2,
    const int* __restrict__ idxp, const int* __restrict__ tdp) {

    __shared__ float smH[2][2][128 * 20];   // [buf][s][t*20+k] : 40.96 KB
    __shared__ float smW[2][2][32 * 20];    // [buf][s][cc*20+k]: 10.24 KB
    __shared__ float smBs[32], smBt[32];

    const int idx = idxp[0];
    const int td  = tdp[0];
    const int i1  = (td >= 0) ? (idx - td) : idx;
    const int i2  = (td >= 0) ? idx        : (idx + td);

    const int c0  = blockIdx.x * 32;
    const int tid = threadIdx.x;
    const int warp = tid >> 5, lane = tid & 31;
    const int wt = warp & 3;          // t-strip of 32
    const int wc = warp >> 2;         // c-strip of 16
    const int g = lane >> 2, tg = lane & 3;

    if (tid < 32) {
        int cp = c0 + tid;
        float b1 = 0.f, b2 = 0.f;
        if (cp < 2 * N_NODES) {
            int c = (cp >> 1) * NFEAT + ((cp & 1) ? i2 : i1);
            b1 = bs2[c]; b2 = bt2[c];
        }
        smBs[tid] = b1; smBt[tid] = b2;
    }

    const uint32_t baseH = (uint32_t)__cvta_generic_to_shared(&smH[0][0][0]);
    const uint32_t baseW = (uint32_t)__cvta_generic_to_shared(&smW[0][0][0]);

    // W gather coords: 1024 elements/stage (32 cc x 16 kk x 2 s), 4 per thread.
    const float* wSrc[4];
    uint32_t     wDst[4];
#pragma unroll
    for (int it = 0; it < 4; it++) {
        int e  = tid + it * 256;
        int s  = e >> 9;
        int cc = (e & 511) >> 4;
        int kk = e & 15;
        int cp = c0 + cc; if (cp >= 2 * N_NODES) cp = 2 * N_NODES - 1;
        long c = (long)(cp >> 1) * NFEAT + ((cp & 1) ? i2 : i1);
        wSrc[it] = (s ? Wt2 : Ws2) + (long)kk * (N_NODES * NFEAT) + c;
        wDst[it] = (uint32_t)(s * 640 + cc * 20 + kk);
    }

#define EMB_ISSUE(st, b)                                                            \
    {                                                                               \
        int kc = (st) * 16;                                                         \
        _Pragma("unroll")                                                           \
        for (int it = 0; it < 4; it++) {                                            \
            int e = tid + it * 256;                                                 \
            int s = e >> 9, row = (e & 511) >> 2, k4 = (e & 3) * 4;                 \
            const float* src = (s ? g_Ht : g_Hs) + row * FC1 + kc + k4;             \
            cp_async16(baseH + ((b) * 5120 + s * 2560 + row * 20 + k4) * 4, src);   \
        }                                                                           \
        _Pragma("unroll")                                                           \
        for (int it = 0; it < 4; it++)                                              \
            cp_async4(baseW + ((b) * 1280 + wDst[it]) * 4,                          \
                      wSrc[it] + (long)kc * (N_NODES * NFEAT));                     \
        asm volatile("cp.async.commit_group;");                                     \
    }

    float accS[2][2][4], accT[2][2][4];
#pragma unroll
    for (int i = 0; i < 2; i++)
#pragma unroll
        for (int j = 0; j < 2; j++)
#pragma unroll
            for (int q = 0; q < 4; q++) { accS[i][j][q] = 0.f; accT[i][j][q] = 0.f; }

    EMB_ISSUE(0, 0);
    for (int st = 0; st < 16; st++) {
        if (st < 15) EMB_ISSUE(st + 1, (st + 1) & 1);
        if (st < 15) { asm volatile("cp.async.wait_group 1;"); }
        else         { asm volatile("cp.async.wait_group 0;"); }
        __syncthreads();
        const float* sHs = &smH[st & 1][0][0];
        const float* sHt = &smH[st & 1][1][0];
        const float* sWs = &smW[st & 1][0][0];
        const float* sWt = &smW[st & 1][1][0];
#pragma unroll
        for (int ks = 0; ks < 2; ks++) {
            int k0 = ks * 8;
            uint32_t aS[2][4], aT[2][4];
#pragma unroll
            for (int i = 0; i < 2; i++) {
                int base = (wt * 32 + i * 16) * 20 + k0;
                aS[i][0] = __float_as_uint(sHs[base + g * 20 + tg]);
                aS[i][1] = __float_as_uint(sHs[base + (g + 8) * 20 + tg]);
                aS[i][2] = __float_as_uint(sHs[base + g * 20 + tg + 4]);
                aS[i][3] = __float_as_uint(sHs[base + (g + 8) * 20 + tg + 4]);
                aT[i][0] = __float_as_uint(sHt[base + g * 20 + tg]);
                aT[i][1] = __float_as_uint(sHt[base + (g + 8) * 20 + tg]);
                aT[i][2] = __float_as_uint(sHt[base + g * 20 + tg + 4]);
                aT[i][3] = __float_as_uint(sHt[base + (g + 8) * 20 + tg + 4]);
            }
            uint32_t bS[2][2], bT[2][2];
#pragma unroll
            for (int j = 0; j < 2; j++) {
                int bb = (wc * 16 + j * 8 + g) * 20 + k0 + tg;
                bS[j][0] = __float_as_uint(sWs[bb]);
                bS[j][1] = __float_as_uint(sWs[bb + 4]);
                bT[j][0] = __float_as_uint(sWt[bb]);
                bT[j][1] = __float_as_uint(sWt[bb + 4]);
            }
#pragma unroll
            for (int i = 0; i < 2; i++)
#pragma unroll
                for (int j = 0; j < 2; j++) {
                    MMA_TF32(accS[i][j], aS[i], bS[j]);
                    MMA_TF32(accT[i][j], aT[i], bT[j]);
                }
        }
        __syncthreads();
    }

#pragma unroll
    for (int i = 0; i < 2; i++)
#pragma unroll
        for (int j = 0; j < 2; j++)
#pragma unroll
            for (int q = 0; q < 4; q++) {
                int t   = wt * 32 + i * 16 + g + ((q & 2) ? 8 : 0);
                int col = wc * 16 + j * 8 + 2 * tg + (q & 1);
                int cp  = c0 + col;
                if (cp < 2 * N_NODES) {
                    float v = fmaxf(accS[i][j][q] + smBs[col], 0.f)
                            + fmaxf(accT[i][j][q] + smBt[col], 0.f);
                    int n = cp >> 1;
                    if (cp & 1) g_U2[n * 128 + t] = to_tf32(v);
                    else        g_U1[n * 128 + t] = to_tf32(v);
                }
            }
}

// ---------------- kernel 4: P = U2 @ B^T via tf32 mma, grid 63 ------------
// block 256 (8 warps: 2 m-strips of 16 x 4 f-strips of 32), m-tile 32
__global__ __launch_bounds__(256) void k_u2b(const float* __restrict__ B) {
    __shared__ float smA[32 * 36];    // [m][g-chunk 32]
    __shared__ float smB[128 * 36];   // [f][g-chunk 32]
    const int m0  = blockIdx.x * 32;
    const int tid = threadIdx.x;
    const int warp = tid >> 5, lane = tid & 31;
    const int wm = warp >> 2;         // m-strip of 16 (0..1)
    const int wf = warp & 3;          // f-strip of 32 (0..3)
    const int g = lane >> 2, tg = lane & 3;

    float acc[4][4];
#pragma unroll
    for (int j = 0; j < 4; j++)
#pragma unroll
        for (int q = 0; q < 4; q++) acc[j][q] = 0.f;

    for (int gc = 0; gc < 128; gc += 32) {
        __syncthreads();
        {   // A: 32 rows x 32 k = 256 float4 loads, 1 per thread
            int row = tid >> 3, k4 = (tid & 7) * 4;
            int m = m0 + row; if (m >= N_NODES) m = N_NODES - 1;
            *(float4*)&smA[row * 36 + k4] = *(const float4*)&g_U2[m * 128 + gc + k4];
        }
#pragma unroll
        for (int it = 0; it < 4; it++) {   // B: 128x32 = 1024 float4, 4/thread
            int e = tid + it * 256;
            int row = e >> 3, k4 = (e & 7) * 4;
            float4 b = *(const float4*)&B[row * 128 + gc + k4];
            b.x = to_tf32(b.x); b.y = to_tf32(b.y); b.z = to_tf32(b.z); b.w = to_tf32(b.w);
            *(float4*)&smB[row * 36 + k4] = b;
        }
        __syncthreads();
#pragma unroll
        for (int ks = 0; ks < 4; ks++) {
            int k0 = ks * 8;
            uint32_t af[4];
            {
                int base = (wm * 16) * 36 + k0;
                af[0] = __float_as_uint(smA[base + g * 36 + tg]);
                af[1] = __float_as_uint(smA[base + (g + 8) * 36 + tg]);
                af[2] = __float_as_uint(smA[base + g * 36 + tg + 4]);
                af[3] = __float_as_uint(smA[base + (g + 8) * 36 + tg + 4]);
            }
            uint32_t bf[4][2];
#pragma unroll
            for (int j = 0; j < 4; j++) {
                int bb = (wf * 32 + j * 8 + g) * 36 + k0 + tg;
                bf[j][0] = __float_as_uint(smB[bb]);
                bf[j][1] = __float_as_uint(smB[bb + 4]);
            }
#pragma unroll
            for (int j = 0; j < 4; j++)
                MMA_TF32(acc[j], af, bf[j]);
        }
    }

#pragma unroll
    for (int j = 0; j < 4; j++) {
        int m = m0 + wm * 16 + g;
        int f = wf * 32 + j * 8 + 2 * tg;
        if (m < N_NODES) {
            float2 v0 = make_float2(to_tf32(acc[j][0]), to_tf32(acc[j][1]));
            *(float2*)&g_P[m * 128 + f] = v0;
        }
        if (m + 8 < N_NODES) {
            float2 v1 = make_float2(to_tf32(acc[j][2]), to_tf32(acc[j][3]));
            *(float2*)&g_P[(m + 8) * 128 + f] = v1;
        }
    }
}

// ---------------- kernel 5: x = U1 @ P^T (tf32, cp.async 2-stage) ---------
__global__ __launch_bounds__(256) void k_gemm(float* __restrict__ out) {
    __shared__ float smA[2][128 * 36];   // [buf][row][k-chunk 32]
    __shared__ float smB[2][128 * 36];
    const int n0 = blockIdx.y * 128;
    const int m0 = blockIdx.x * 128;
    const int tid = threadIdx.x;
    const int warp = tid >> 5, lane = tid & 31;
    const int wn = warp & 3;
    const int wm = warp >> 2;
    const int g = lane >> 2, tg = lane & 3;
    const int lrow = tid >> 3, lkk = (tid & 7) * 4;

    const uint32_t baseA = (uint32_t)__cvta_generic_to_shared(&smA[0][0]);
    const uint32_t baseB = (uint32_t)__cvta_generic_to_shared(&smB[0][0]);

    float acc[2][8][4];
#pragma unroll
    for (int i = 0; i < 2; i++)
#pragma unroll
        for (int j = 0; j < 8; j++)
#pragma unroll
            for (int q = 0; q < 4; q++) acc[i][j][q] = 0.f;

#define GEMM_ISSUE(s, b)                                                            \
    {                                                                               \
        _Pragma("unroll")                                                           \
        for (int it = 0; it < 4; it++) {                                            \
            int row = lrow + it * 32;                                               \
            int gn = n0 + row, gm = m0 + row;                                       \
            int okA = (gn < N_NODES) ? 16 : 0;                                      \
            int okB = (gm < N_NODES) ? 16 : 0;                                      \
            int cn = (gn < N_NODES) ? gn : 0;                                       \
            int cm = (gm < N_NODES) ? gm : 0;                                       \
            cp_async16z(baseA + ((b) * 4608 + row * 36 + lkk) * 4,                  \
                        &g_U1[(long)cn * 128 + (s) * 32 + lkk], okA);               \
            cp_async16z(baseB + ((b) * 4608 + row * 36 + lkk) * 4,                  \
                        &g_P [(long)cm * 128 + (s) * 32 + lkk], okB);               \
        }                                                                           \
        asm volatile("cp.async.commit_group;");                                     \
    }

    GEMM_ISSUE(0, 0);
    for (int kc = 0; kc < 4; kc++) {
        if (kc < 3) GEMM_ISSUE(kc + 1, (kc + 1) & 1);
        if (kc < 3) { asm volatile("cp.async.wait_group 1;"); }
        else        { asm volatile("cp.async.wait_group 0;"); }
        __syncthreads();
        const float* sA = smA[kc & 1];
        const float* sB = smB[kc & 1];
#pragma unroll
        for (int ks = 0; ks < 4; ks++) {
            int k0 = ks * 8;
            uint32_t af[2][4];
#pragma unroll
            for (int i = 0; i < 2; i++) {
                int base = (wn * 32 + i * 16) * 36 + k0;
                af[i][0] = __float_as_uint(sA[base + g * 36 + tg]);
                af[i][1] = __float_as_uint(sA[base + (g + 8) * 36 + tg]);
                af[i][2] = __float_as_uint(sA[base + g * 36 + tg + 4]);
                af[i][3] = __float_as_uint(sA[base + (g + 8) * 36 + tg + 4]);
            }
            uint32_t bf[8][2];
#pragma unroll
            for (int j = 0; j < 8; j++) {
                int bb = (wm * 64 + j * 8 + g) * 36 + k0 + tg;
                bf[j][0] = __float_as_uint(sB[bb]);
                bf[j][1] = __float_as_uint(sB[bb + 4]);
            }
#pragma unroll
            for (int i = 0; i < 2; i++)
#pragma unroll
                for (int j = 0; j < 8; j++)
                    MMA_TF32(acc[i][j], af[i], bf[j]);
        }
        __syncthreads();
    }

#pragma unroll
    for (int i = 0; i < 2; i++) {
#pragma unroll
        for (int j = 0; j < 8; j++) {
            int n = n0 + wn * 32 + i * 16 + g;
            int m = m0 + wm * 64 + j * 8 + 2 * tg;
            if (m < N_NODES) {
                float2 v0, v1;
                v0.x = (acc[i][j][0] >= DELTA_MIN) ? acc[i][j][0] : 0.f;
                v0.y = (acc[i][j][1] >= DELTA_MIN) ? acc[i][j][1] : 0.f;
                v1.x = (acc[i][j][2] >= DELTA_MIN) ? acc[i][j][2] : 0.f;
                v1.y = (acc[i][j][3] >= DELTA_MIN) ? acc[i][j][3] : 0.f;
                if (n < N_NODES)     *(float2*)&out[(long)n * N_NODES + m] = v0;
                if (n + 8 < N_NODES) *(float2*)&out[(long)(n + 8) * N_NODES + m] = v1;
            }
        }
    }
}

// ---------------- kernel 6: in-place row softmax (float4) -----------------
__global__ void k_softmax(float* __restrict__ out) {
    const int row = blockIdx.x;
    float* p = out + (long)row * N_NODES;
    const int tid = threadIdx.x;
    const bool act = tid < 250;
    __shared__ float redM[8];
    __shared__ float redS[8];

    float4 v0, v1;
    float mx = -1e30f;
    if (act) {
        v0 = *(const float4*)&p[tid * 8];
        v1 = *(const float4*)&p[tid * 8 + 4];
        mx = fmaxf(fmaxf(fmaxf(v0.x, v0.y), fmaxf(v0.z, v0.w)),
                   fmaxf(fmaxf(v1.x, v1.y), fmaxf(v1.z, v1.w)));
    }
#pragma unroll
    for (int o = 16; o; o >>= 1) mx = fmaxf(mx, __shfl_xor_sync(0xFFFFFFFFu, mx, o));
    if ((tid & 31) == 0) redM[tid >> 5] = mx;
    __syncthreads();
    float gmax = redM[0];
#pragma unroll
    for (int w = 1; w < 8; w++) gmax = fmaxf(gmax, redM[w]);

    float s = 0.f;
    if (act) {
        v0.x = __expf(v0.x - gmax); v0.y = __expf(v0.y - gmax);
        v0.z = __expf(v0.z - gmax); v0.w = __expf(v0.w - gmax);
        v1.x = __expf(v1.x - gmax); v1.y = __expf(v1.y - gmax);
        v1.z = __expf(v1.z - gmax); v1.w = __expf(v1.w - gmax);
        s = v0.x + v0.y + v0.z + v0.w + v1.x + v1.y + v1.z + v1.w;
    }
#pragma unroll
    for (int o = 16; o; o >>= 1) s += __shfl_xor_sync(0xFFFFFFFFu, s, o);
    if ((tid & 31) == 0) redS[tid >> 5] = s;
    __syncthreads();
    float tot = 0.f;
#pragma unroll
    for (int w = 0; w < 8; w++) tot += redS[w];
    float inv = 1.f / tot;
    if (act) {
        v0.x *= inv; v0.y *= inv; v0.z *= inv; v0.w *= inv;
        v1.x *= inv; v1.y *= inv; v1.z *= inv; v1.w *= inv;
        *(float4*)&p[tid * 8]     = v0;
        *(float4*)&p[tid * 8 + 4] = v1;
    }
}

// ---------------- launch ---------------------------------------------------
extern "C" void kernel_launch(void* const* d_in, const int* in_sizes, int n_in,
                              void* d_out, int out_size) {
    const float* tf   = (const float*)d_in[0];
    const float* li   = (const float*)d_in[1];
    const float* Ws1  = (const float*)d_in[2];
    const float* bs1  = (const float*)d_in[3];
    const float* Ws2  = (const float*)d_in[4];
    const float* bs2  = (const float*)d_in[5];
    const float* Wt1  = (const float*)d_in[6];
    const float* bt1  = (const float*)d_in[7];
    const float* Wt2  = (const float*)d_in[8];
    const float* bt2  = (const float*)d_in[9];
    const float* B    = (const float*)d_in[10];
    const int*   idxp = (const int*)d_in[11];
    const int*   tdp  = (const int*)d_in[12];
    float* out = (float*)d_out;

    k_hid_s  <<<dim3(8, 25), 256>>>(li, Ws1);
    k_hid_fin<<<128, 256>>>(tf, Wt1, bs1, bt1);
    k_embed  <<<126, 256>>>(Ws2, Wt2, bs2, bt2, idxp, tdp);
    k_u2b    <<<63, 256>>>(B);
    k_gemm   <<<dim3(16, 16), 256>>>(out);
    k_softmax<<<2000, 256>>>(out);
}

// round 10
// speedup vs baseline: 1.7228x; 1.0773x over previous
#include <cuda_runtime.h>
#include <math.h>
#include <stdint.h>

#define N_NODES 2000
#define NFEAT   128
#define LB      128
#define TFEAT   36
#define FC1     256
#define DELTA_MIN 0.05f

// ---------------- scratch (device globals; no allocation) ----------------
__device__ float g_accP[25][FC1 * LB];     // split-K partials, [split][t*256 + k]
__device__ float g_Hs[LB * FC1];           // relu spatial hidden, [t][k] (tf32)
__device__ float g_Ht[LB * FC1];           // relu temporal hidden, [t][k] (tf32)
__device__ float g_U1[N_NODES * LB];       // U[:,:,i1]  [n][t]  (tf32)
__device__ float g_P [N_NODES * LB];       // U2 @ B^T   [m][f]

__device__ __forceinline__ float to_tf32(float x) {
    uint32_t u;
    asm("cvt.rna.tf32.f32 %0, %1;" : "=r"(u) : "f"(x));
    return __uint_as_float(u);
}
__device__ __forceinline__ void cp_async16(uint32_t dst, const void* src) {
    asm volatile("cp.async.ca.shared.global [%0], [%1], 16;" :: "r"(dst), "l"(src));
}
__device__ __forceinline__ void cp_async16z(uint32_t dst, const void* src, int ssize) {
    asm volatile("cp.async.ca.shared.global [%0], [%1], 16, %2;"
                 :: "r"(dst), "l"(src), "r"(ssize));
}
__device__ __forceinline__ void cp_async4(uint32_t dst, const void* src) {
    asm volatile("cp.async.ca.shared.global [%0], [%1], 4;" :: "r"(dst), "l"(src));
}

#define MMA_TF32(c, a, b)                                                          \
    asm volatile("mma.sync.aligned.m16n8k8.row.col.f32.tf32.tf32.f32 "             \
                 "{%0,%1,%2,%3},{%4,%5,%6,%7},{%8,%9},{%0,%1,%2,%3};"              \
                 : "+f"(c[0]), "+f"(c[1]), "+f"(c[2]), "+f"(c[3])                  \
                 : "r"(a[0]), "r"(a[1]), "r"(a[2]), "r"(a[3]), "r"(b[0]), "r"(b[1]))

// ---------------- kernel 1: spatial hidden, split-K, coalesced ------------
// grid (8 k-tiles of 32, 25 j-splits of 80), block 256
__global__ __launch_bounds__(256) void k_hid_s(const float* __restrict__ li,
                                               const float* __restrict__ Ws1) {
    __shared__ float smA[16 * 132];
    __shared__ float smW[16 * 36];
    const int k0 = blockIdx.x * 32;
    const int j0 = blockIdx.y * 80;
    const int tid = threadIdx.x;
    const int tx = tid & 7;
    const int ty = tid >> 3;

    float acc[4][4];
#pragma unroll
    for (int u = 0; u < 4; u++)
#pragma unroll
        for (int v = 0; v < 4; v++) acc[u][v] = 0.f;

    for (int jb = 0; jb < 80; jb += 16) {
        __syncthreads();
#pragma unroll
        for (int it = 0; it < 8; it++) {
            int e = tid + it * 256;
            int t = e >> 4, jj = e & 15;
            smA[jj * 132 + t] = li[t * N_NODES + j0 + jb + jj];
        }
#pragma unroll
        for (int it = 0; it < 2; it++) {
            int e = tid + it * 256;
            int jj = e >> 5, kk = e & 31;
            smW[jj * 36 + kk] = Ws1[(j0 + jb + jj) * FC1 + k0 + kk];
        }
        __syncthreads();
#pragma unroll
        for (int jj = 0; jj < 16; jj++) {
            float4 a = *(const float4*)&smA[jj * 132 + ty * 4];
            float4 w = *(const float4*)&smW[jj * 36 + tx * 4];
            float av[4] = {a.x, a.y, a.z, a.w};
            float wv[4] = {w.x, w.y, w.z, w.w};
#pragma unroll
            for (int u = 0; u < 4; u++)
#pragma unroll
                for (int v = 0; v < 4; v++) acc[u][v] += av[u] * wv[v];
        }
    }
    const int sp = blockIdx.y;
#pragma unroll
    for (int u = 0; u < 4; u++) {
        int t = ty * 4 + u;
        float4 v = make_float4(acc[u][0], acc[u][1], acc[u][2], acc[u][3]);
        *(float4*)&g_accP[sp][t * FC1 + k0 + tx * 4] = v;
    }
}

// ---------------- kernel 2: finalize hidden, store [t][k] tf32 ------------
// grid 128 (t), block 256 (k)
__global__ void k_hid_fin(const float* __restrict__ tf, const float* __restrict__ Wt1,
                          const float* __restrict__ bs1, const float* __restrict__ bt1) {
    const int t = blockIdx.x;
    const int k = threadIdx.x;
    __shared__ float stf[TFEAT];
    if (k < TFEAT) stf[k] = tf[t * TFEAT + k];

    float hs = bs1[k];
#pragma unroll
    for (int s = 0; s < 25; s++) hs += g_accP[s][t * FC1 + k];
    g_Hs[t * FC1 + k] = to_tf32(fmaxf(hs, 0.f));

    __syncthreads();
    float a = bt1[k];
#pragma unroll
    for (int j = 0; j < TFEAT; j++)
        a += stf[j] * Wt1[j * FC1 + k];
    g_Ht[t * FC1 + k] = to_tf32(fmaxf(a, 0.f));
}

// ---------------- kernel 3: embed (fused W gather) + fused P --------------
// grid 126 (32 c' = 16 nodes each), block 256 (8 warps: 4 t-strips x 2 c-strips)
__global__ __launch_bounds__(256) void k_embed(
    const float* __restrict__ Ws2, const float* __restrict__ Wt2,
    const float* __restrict__ bs2, const float* __restrict__ bt2,
    const float* __restrict__ B,
    const int* __restrict__ idxp, const int* __restrict__ tdp) {

    __shared__ float smH[2][2][128 * 20];   // [buf][s][t*20+k] : 40.96 KB
    __shared__ float smW[2][2][32 * 20];    // [buf][s][cc*20+k]: 10.24 KB
    __shared__ float smBs[32], smBt[32];

    const int idx = idxp[0];
    const int td  = tdp[0];
    const int i1  = (td >= 0) ? (idx - td) : idx;
    const int i2  = (td >= 0) ? idx        : (idx + td);

    const int c0  = blockIdx.x * 32;
    const int tid = threadIdx.x;
    const int warp = tid >> 5, lane = tid & 31;
    const int wt = warp & 3;          // t-strip of 32
    const int wc = warp >> 2;         // c-strip of 16
    const int g = lane >> 2, tg = lane & 3;

    if (tid < 32) {
        int cp = c0 + tid;
        float b1 = 0.f, b2 = 0.f;
        if (cp < 2 * N_NODES) {
            int c = (cp >> 1) * NFEAT + ((cp & 1) ? i2 : i1);
            b1 = bs2[c]; b2 = bt2[c];
        }
        smBs[tid] = b1; smBt[tid] = b2;
    }

    const uint32_t baseH = (uint32_t)__cvta_generic_to_shared(&smH[0][0][0]);
    const uint32_t baseW = (uint32_t)__cvta_generic_to_shared(&smW[0][0][0]);

    // W gather coords: 1024 elements/stage (32 cc x 16 kk x 2 s), 4 per thread.
    const float* wSrc[4];
    uint32_t     wDst[4];
#pragma unroll
    for (int it = 0; it < 4; it++) {
        int e  = tid + it * 256;
        int s  = e >> 9;
        int cc = (e & 511) >> 4;
        int kk = e & 15;
        int cp = c0 + cc; if (cp >= 2 * N_NODES) cp = 2 * N_NODES - 1;
        long c = (long)(cp >> 1) * NFEAT + ((cp & 1) ? i2 : i1);
        wSrc[it] = (s ? Wt2 : Ws2) + (long)kk * (N_NODES * NFEAT) + c;
        wDst[it] = (uint32_t)(s * 640 + cc * 20 + kk);
    }

#define EMB_ISSUE(st, b)                                                            \
    {                                                                               \
        int kc = (st) * 16;                                                         \
        _Pragma("unroll")                                                           \
        for (int it = 0; it < 4; it++) {                                            \
            int e = tid + it * 256;                                                 \
            int s = e >> 9, row = (e & 511) >> 2, k4 = (e & 3) * 4;                 \
            const float* src = (s ? g_Ht : g_Hs) + row * FC1 + kc + k4;             \
            cp_async16(baseH + ((b) * 5120 + s * 2560 + row * 20 + k4) * 4, src);   \
        }                                                                           \
        _Pragma("unroll")                                                           \
        for (int it = 0; it < 4; it++)                                              \
            cp_async4(baseW + ((b) * 1280 + wDst[it]) * 4,                          \
                      wSrc[it] + (long)kc * (N_NODES * NFEAT));                     \
        asm volatile("cp.async.commit_group;");                                     \
    }

    float accS[2][2][4], accT[2][2][4];
#pragma unroll
    for (int i = 0; i < 2; i++)
#pragma unroll
        for (int j = 0; j < 2; j++)
#pragma unroll
            for (int q = 0; q < 4; q++) { accS[i][j][q] = 0.f; accT[i][j][q] = 0.f; }

    EMB_ISSUE(0, 0);
    for (int st = 0; st < 16; st++) {
        if (st < 15) EMB_ISSUE(st + 1, (st + 1) & 1);
        if (st < 15) { asm volatile("cp.async.wait_group 1;"); }
        else         { asm volatile("cp.async.wait_group 0;"); }
        __syncthreads();
        const float* sHs = &smH[st & 1][0][0];
        const float* sHt = &smH[st & 1][1][0];
        const float* sWs = &smW[st & 1][0][0];
        const float* sWt = &smW[st & 1][1][0];
#pragma unroll
        for (int ks = 0; ks < 2; ks++) {
            int k0 = ks * 8;
            uint32_t aS[2][4], aT[2][4];
#pragma unroll
            for (int i = 0; i < 2; i++) {
                int base = (wt * 32 + i * 16) * 20 + k0;
                aS[i][0] = __float_as_uint(sHs[base + g * 20 + tg]);
                aS[i][1] = __float_as_uint(sHs[base + (g + 8) * 20 + tg]);
                aS[i][2] = __float_as_uint(sHs[base + g * 20 + tg + 4]);
                aS[i][3] = __float_as_uint(sHs[base + (g + 8) * 20 + tg + 4]);
                aT[i][0] = __float_as_uint(sHt[base + g * 20 + tg]);
                aT[i][1] = __float_as_uint(sHt[base + (g + 8) * 20 + tg]);
                aT[i][2] = __float_as_uint(sHt[base + g * 20 + tg + 4]);
                aT[i][3] = __float_as_uint(sHt[base + (g + 8) * 20 + tg + 4]);
            }
            uint32_t bS[2][2], bT[2][2];
#pragma unroll
            for (int j = 0; j < 2; j++) {
                int bb = (wc * 16 + j * 8 + g) * 20 + k0 + tg;
                bS[j][0] = __float_as_uint(sWs[bb]);
                bS[j][1] = __float_as_uint(sWs[bb + 4]);
                bT[j][0] = __float_as_uint(sWt[bb]);
                bT[j][1] = __float_as_uint(sWt[bb + 4]);
            }
#pragma unroll
            for (int i = 0; i < 2; i++)
#pragma unroll
                for (int j = 0; j < 2; j++) {
                    MMA_TF32(accS[i][j], aS[i], bS[j]);
                    MMA_TF32(accT[i][j], aT[i], bT[j]);
                }
        }
        __syncthreads();
    }

    // ---- epilogue: relu sum; U1 -> global, U2 -> smem (reuse smW) --------
    float* smU2 = &smW[0][0][0];     // [16 nodes][132 t] = 2112 floats (cap 2560)
#pragma unroll
    for (int i = 0; i < 2; i++)
#pragma unroll
        for (int j = 0; j < 2; j++)
#pragma unroll
            for (int q = 0; q < 4; q++) {
                int t   = wt * 32 + i * 16 + g + ((q & 2) ? 8 : 0);
                int col = wc * 16 + j * 8 + 2 * tg + (q & 1);
                int cp  = c0 + col;
                float v = fmaxf(accS[i][j][q] + smBs[col], 0.f)
                        + fmaxf(accT[i][j][q] + smBt[col], 0.f);
                if (cp & 1) {
                    smU2[(col >> 1) * 132 + t] = v;
                } else if (cp < 2 * N_NODES) {
                    g_U1[(cp >> 1) * 128 + t] = to_tf32(v);
                }
            }
    __syncthreads();

    // ---- fused P = U2 @ B^T for this block's 16 nodes --------------------
    // warps: warp w -> f-strip of 16 (2 n8 tiles). A = smU2 [16 m][128 t].
    float* smBm = &smH[0][0][0];     // [128 f][36] = 4608 floats (cap 10240)
    float pacc[2][4];
#pragma unroll
    for (int j = 0; j < 2; j++)
#pragma unroll
        for (int q = 0; q < 4; q++) pacc[j][q] = 0.f;

    for (int gc = 0; gc < 128; gc += 32) {
        __syncthreads();
#pragma unroll
        for (int it = 0; it < 4; it++) {
            int e = tid + it * 256;
            int f = e >> 3, k4 = (e & 7) * 4;
            *(float4*)&smBm[f * 36 + k4] = *(const float4*)&B[f * 128 + gc + k4];
        }
        __syncthreads();
#pragma unroll
        for (int ks = 0; ks < 4; ks++) {
            int k0 = ks * 8;
            uint32_t af[4];
            af[0] = __float_as_uint(smU2[g * 132 + gc + k0 + tg]);
            af[1] = __float_as_uint(smU2[(g + 8) * 132 + gc + k0 + tg]);
            af[2] = __float_as_uint(smU2[g * 132 + gc + k0 + tg + 4]);
            af[3] = __float_as_uint(smU2[(g + 8) * 132 + gc + k0 + tg + 4]);
            uint32_t bf[2][2];
#pragma unroll
            for (int j = 0; j < 2; j++) {
                int bb = (warp * 16 + j * 8 + g) * 36 + k0 + tg;
                bf[j][0] = __float_as_uint(smBm[bb]);
                bf[j][1] = __float_as_uint(smBm[bb + 4]);
            }
#pragma unroll
            for (int j = 0; j < 2; j++)
                MMA_TF32(pacc[j], af, bf[j]);
        }
    }

    const int n0n = c0 >> 1;
#pragma unroll
    for (int j = 0; j < 2; j++) {
        int f = warp * 16 + j * 8 + 2 * tg;
        if (n0n + g < N_NODES)
            *(float2*)&g_P[(n0n + g) * 128 + f] = make_float2(pacc[j][0], pacc[j][1]);
        if (n0n + g + 8 < N_NODES)
            *(float2*)&g_P[(n0n + g + 8) * 128 + f] = make_float2(pacc[j][2], pacc[j][3]);
    }
}

// ---------------- kernel 4: x = U1 @ P^T (tf32, cp.async 2-stage) ---------
__global__ __launch_bounds__(256) void k_gemm(float* __restrict__ out) {
    __shared__ float smA[2][128 * 36];   // [buf][row][k-chunk 32]
    __shared__ float smB[2][128 * 36];
    const int n0 = blockIdx.y * 128;
    const int m0 = blockIdx.x * 128;
    const int tid = threadIdx.x;
    const int warp = tid >> 5, lane = tid & 31;
    const int wn = warp & 3;
    const int wm = warp >> 2;
    const int g = lane >> 2, tg = lane & 3;
    const int lrow = tid >> 3, lkk = (tid & 7) * 4;

    const uint32_t baseA = (uint32_t)__cvta_generic_to_shared(&smA[0][0]);
    const uint32_t baseB = (uint32_t)__cvta_generic_to_shared(&smB[0][0]);

    float acc[2][8][4];
#pragma unroll
    for (int i = 0; i < 2; i++)
#pragma unroll
        for (int j = 0; j < 8; j++)
#pragma unroll
            for (int q = 0; q < 4; q++) acc[i][j][q] = 0.f;

#define GEMM_ISSUE(s, b)                                                            \
    {                                                                               \
        _Pragma("unroll")                                                           \
        for (int it = 0; it < 4; it++) {                                            \
            int row = lrow + it * 32;                                               \
            int gn = n0 + row, gm = m0 + row;                                       \
            int okA = (gn < N_NODES) ? 16 : 0;                                      \
            int okB = (gm < N_NODES) ? 16 : 0;                                      \
            int cn = (gn < N_NODES) ? gn : 0;                                       \
            int cm = (gm < N_NODES) ? gm : 0;                                       \
            cp_async16z(baseA + ((b) * 4608 + row * 36 + lkk) * 4,                  \
                        &g_U1[(long)cn * 128 + (s) * 32 + lkk], okA);               \
            cp_async16z(baseB + ((b) * 4608 + row * 36 + lkk) * 4,                  \
                        &g_P [(long)cm * 128 + (s) * 32 + lkk], okB);               \
        }                                                                           \
        asm volatile("cp.async.commit_group;");                                     \
    }

    GEMM_ISSUE(0, 0);
    for (int kc = 0; kc < 4; kc++) {
        if (kc < 3) GEMM_ISSUE(kc + 1, (kc + 1) & 1);
        if (kc < 3) { asm volatile("cp.async.wait_group 1;"); }
        else        { asm volatile("cp.async.wait_group 0;"); }
        __syncthreads();
        const float* sA = smA[kc & 1];
        const float* sB = smB[kc & 1];
#pragma unroll
        for (int ks = 0; ks < 4; ks++) {
            int k0 = ks * 8;
            uint32_t af[2][4];
#pragma unroll
            for (int i = 0; i < 2; i++) {
                int base = (wn * 32 + i * 16) * 36 + k0;
                af[i][0] = __float_as_uint(sA[base + g * 36 + tg]);
                af[i][1] = __float_as_uint(sA[base + (g + 8) * 36 + tg]);
                af[i][2] = __float_as_uint(sA[base + g * 36 + tg + 4]);
                af[i][3] = __float_as_uint(sA[base + (g + 8) * 36 + tg + 4]);
            }
            uint32_t bf[8][2];
#pragma unroll
            for (int j = 0; j < 8; j++) {
                int bb = (wm * 64 + j * 8 + g) * 36 + k0 + tg;
                bf[j][0] = __float_as_uint(sB[bb]);
                bf[j][1] = __float_as_uint(sB[bb + 4]);
            }
#pragma unroll
            for (int i = 0; i < 2; i++)
#pragma unroll
                for (int j = 0; j < 8; j++)
                    MMA_TF32(acc[i][j], af[i], bf[j]);
        }
        __syncthreads();
    }

#pragma unroll
    for (int i = 0; i < 2; i++) {
#pragma unroll
        for (int j = 0; j < 8; j++) {
            int n = n0 + wn * 32 + i * 16 + g;
            int m = m0 + wm * 64 + j * 8 + 2 * tg;
            if (m < N_NODES) {
                float2 v0, v1;
                v0.x = (acc[i][j][0] >= DELTA_MIN) ? acc[i][j][0] : 0.f;
                v0.y = (acc[i][j][1] >= DELTA_MIN) ? acc[i][j][1] : 0.f;
                v1.x = (acc[i][j][2] >= DELTA_MIN) ? acc[i][j][2] : 0.f;
                v1.y = (acc[i][j][3] >= DELTA_MIN) ? acc[i][j][3] : 0.f;
                if (n < N_NODES)     *(float2*)&out[(long)n * N_NODES + m] = v0;
                if (n + 8 < N_NODES) *(float2*)&out[(long)(n + 8) * N_NODES + m] = v1;
            }
        }
    }
}

// ---------------- kernel 5: in-place row softmax (float4) -----------------
__global__ void k_softmax(float* __restrict__ out) {
    const int row = blockIdx.x;
    float* p = out + (long)row * N_NODES;
    const int tid = threadIdx.x;
    const bool act = tid < 250;
    __shared__ float redM[8];
    __shared__ float redS[8];

    float4 v0, v1;
    float mx = -1e30f;
    if (act) {
        v0 = *(const float4*)&p[tid * 8];
        v1 = *(const float4*)&p[tid * 8 + 4];
        mx = fmaxf(fmaxf(fmaxf(v0.x, v0.y), fmaxf(v0.z, v0.w)),
                   fmaxf(fmaxf(v1.x, v1.y), fmaxf(v1.z, v1.w)));
    }
#pragma unroll
    for (int o = 16; o; o >>= 1) mx = fmaxf(mx, __shfl_xor_sync(0xFFFFFFFFu, mx, o));
    if ((tid & 31) == 0) redM[tid >> 5] = mx;
    __syncthreads();
    float gmax = redM[0];
#pragma unroll
    for (int w = 1; w < 8; w++) gmax = fmaxf(gmax, redM[w]);

    float s = 0.f;
    if (act) {
        v0.x = __expf(v0.x - gmax); v0.y = __expf(v0.y - gmax);
        v0.z = __expf(v0.z - gmax); v0.w = __expf(v0.w - gmax);
        v1.x = __expf(v1.x - gmax); v1.y = __expf(v1.y - gmax);
        v1.z = __expf(v1.z - gmax); v1.w = __expf(v1.w - gmax);
        s = v0.x + v0.y + v0.z + v0.w + v1.x + v1.y + v1.z + v1.w;
    }
#pragma unroll
    for (int o = 16; o; o >>= 1) s += __shfl_xor_sync(0xFFFFFFFFu, s, o);
    if ((tid & 31) == 0) redS[tid >> 5] = s;
    __syncthreads();
    float tot = 0.f;
#pragma unroll
    for (int w = 0; w < 8; w++) tot += redS[w];
    float inv = 1.f / tot;
    if (act) {
        v0.x *= inv; v0.y *= inv; v0.z *= inv; v0.w *= inv;
        v1.x *= inv; v1.y *= inv; v1.z *= inv; v1.w *= inv;
        *(float4*)&p[tid * 8]     = v0;
        *(float4*)&p[tid * 8 + 4] = v1;
    }
}

// ---------------- launch ---------------------------------------------------
extern "C" void kernel_launch(void* const* d_in, const int* in_sizes, int n_in,
                              void* d_out, int out_size) {
    const float* tf   = (const float*)d_in[0];
    const float* li   = (const float*)d_in[1];
    const float* Ws1  = (const float*)d_in[2];
    const float* bs1  = (const float*)d_in[3];
    const float* Ws2  = (const float*)d_in[4];
    const float* bs2  = (const float*)d_in[5];
    const float* Wt1  = (const float*)d_in[6];
    const float* bt1  = (const float*)d_in[7];
    const float* Wt2  = (const float*)d_in[8];
    const float* bt2  = (const float*)d_in[9];
    const float* B    = (const float*)d_in[10];
    const int*   idxp = (const int*)d_in[11];
    const int*   tdp  = (const int*)d_in[12];
    float* out = (float*)d_out;

    k_hid_s  <<<dim3(8, 25), 256>>>(li, Ws1);
    k_hid_fin<<<128, 256>>>(tf, Wt1, bs1, bt1);
    k_embed  <<<126, 256>>>(Ws2, Wt2, bs2, bt2, B, idxp, tdp);
    k_gemm   <<<dim3(16, 16), 256>>>(out);
    k_softmax<<<2000, 256>>>(out);
}